// round 3
// baseline (speedup 1.0000x reference)
#include <cuda_runtime.h>

#define FULLMASK 0xffffffffu

typedef unsigned long long u64;

__device__ __forceinline__ float silu_f(float x) {
    return x / (1.0f + __expf(-x));
}

__device__ __forceinline__ u64 pack2(float a, float b) {
    u64 r; asm("mov.b64 %0, {%1,%2};" : "=l"(r) : "f"(a), "f"(b)); return r;
}
__device__ __forceinline__ void unpack2(u64 v, float& a, float& b) {
    asm("mov.b64 {%0,%1}, %2;" : "=f"(a), "=f"(b) : "l"(v));
}
__device__ __forceinline__ u64 ffma2(u64 a, u64 b, u64 c) {
    u64 d; asm("fma.rn.f32x2 %0, %1, %2, %3;" : "=l"(d) : "l"(a), "l"(b), "l"(c));
    return d;
}

// ---------------------------------------------------------------------------
// Edge kernel (f32x2 packed): one filter net over all edges.
// One warp handles 8 edges at a time; lane owns 4 consecutive output columns
// held as 2 f32x2 packs. Broadcast activations (rbf / h1 / e1) are staged in
// smem pre-duplicated as (h,h) u64 pairs so the mainloop is pure
// LDS.128 + fma.rn.f32x2 with no repacking.
// ---------------------------------------------------------------------------
__global__ __launch_bounds__(384, 1)
void edge_filter_kernel(const float* __restrict__ evf,
                        const int*   __restrict__ senders,
                        const int*   __restrict__ receivers,
                        const float* __restrict__ lengths,
                        const float* __restrict__ wr1, const float* __restrict__ br1,
                        const float* __restrict__ wr2, const float* __restrict__ br2,
                        const float* __restrict__ we1, const float* __restrict__ be1,
                        const float* __restrict__ we2, const float* __restrict__ be2,
                        float* __restrict__ outw, int E)
{
    extern __shared__ char smraw[];
    float* wr1s = (float*)smraw;         // 32*128  = 4096
    float* wr2s = wr1s + 4096;           // 128*128 = 16384
    float* we2s = wr2s + 16384;          // 32*128  = 4096
    float* we1s = we2s + 4096;           // 128
    float* br1s = we1s + 128;            // 128
    float* br2s = br1s + 128;            // 128
    float* be2s = br2s + 128;            // 128
    float* be1s = be2s + 128;            // 32
    // u64 region starts at float offset 25120 (byte 100480, 16B aligned)
    u64* dupbase = (u64*)(smraw + 100480);
    // per warp: h1dup[8*128] + sdup[8*32]  = 1280 u64 = 10KB

    const int tid = threadIdx.x;
    for (int i = tid; i < 4096;  i += 384) wr1s[i] = wr1[i];
    for (int i = tid; i < 16384; i += 384) wr2s[i] = wr2[i];
    for (int i = tid; i < 4096;  i += 384) we2s[i] = we2[i];
    if (tid < 128) { we1s[tid] = we1[tid]; br1s[tid] = br1[tid];
                     br2s[tid] = br2[tid]; be2s[tid] = be2[tid]; }
    if (tid < 32)  be1s[tid] = be1[tid];
    __syncthreads();

    const int lane = tid & 31;
    const int warp = tid >> 5;
    u64* h1dup = dupbase + warp * 1280;
    u64* sdup  = h1dup + 1024;

    const int c0 = lane * 4;
    const float4 br1v = *(const float4*)&br1s[c0];
    const float4 br2v = *(const float4*)&br2s[c0];
    const float4 be2v = *(const float4*)&be2s[c0];
    const float  be1v = be1s[lane];
    float we1l[4];
    #pragma unroll
    for (int q = 0; q < 4; q++) we1l[q] = we1s[q * 32 + lane];

    const float center = (float)lane * (5.0f / 31.0f);
    const float GAMMA  = 0.5f * (31.0f / 5.0f) * (31.0f / 5.0f);
    const int SEG[16] = {0,1,1,1,2,2,2,2,2,3,3,3,3,3,3,3};

    const int nGroups = (E + 7) >> 3;
    const int gstride = gridDim.x * 12;

    for (int g = blockIdx.x * 12 + warp; g < nGroups; g += gstride) {
        const int ebase = g * 8;

        int   sI[8], rI[8];
        float dI[8];
        #pragma unroll
        for (int ei = 0; ei < 8; ei++) {
            int e  = ebase + ei;
            int ee = (e < E) ? e : (E - 1);
            sI[ei] = senders[ee];
            rI[ei] = receivers[ee];
            dI[ei] = lengths[ee];
        }

        // ev_diff invariants: 4 seg-sums per edge, broadcast to all lanes
        float inv[8][4];
        #pragma unroll
        for (int ei = 0; ei < 8; ei++) {
            float p = 0.0f;
            if (lane < 16) {
                float a = evf[sI[ei] * 16 + lane] - evf[rI[ei] * 16 + lane];
                p = a * a;
            }
            float s0 = 0.f, s1 = 0.f, s2 = 0.f, s3 = 0.f;
            #pragma unroll
            for (int k = 0; k < 16; k++) {
                float v = __shfl_sync(FULLMASK, p, k);
                if (SEG[k] == 0) s0 += v;
                else if (SEG[k] == 1) s1 += v;
                else if (SEG[k] == 2) s2 += v;
                else s3 += v;
            }
            inv[ei][0] = s0; inv[ei][1] = s1; inv[ei][2] = s2; inv[ei][3] = s3;
        }

        // rbf: lane j holds rbf_j; e1: lane holds col `lane`
        float rbf[8], e1r[8];
        #pragma unroll
        for (int ei = 0; ei < 8; ei++) {
            float t = dI[ei] - center;
            rbf[ei] = __expf(-GAMMA * t * t);
            float a = be1v;
            #pragma unroll
            for (int q = 0; q < 4; q++) a = fmaf(inv[ei][q], we1l[q], a);
            e1r[ei] = silu_f(a);
        }

        // stage rbf duplicated into sdup
        #pragma unroll
        for (int ei = 0; ei < 8; ei++)
            sdup[ei * 32 + lane] = pack2(rbf[ei], rbf[ei]);
        __syncwarp();

        // stage 1: h1 = silu(rbf @ wr1 + br1)   (K=32)
        u64 a1[8][2];
        #pragma unroll
        for (int ei = 0; ei < 8; ei++) {
            a1[ei][0] = pack2(br1v.x, br1v.y);
            a1[ei][1] = pack2(br1v.z, br1v.w);
        }
        #pragma unroll 4
        for (int j = 0; j < 32; j += 2) {
            ulonglong2 wA = *(const ulonglong2*)&wr1s[j * 128 + c0];
            ulonglong2 wB = *(const ulonglong2*)&wr1s[(j + 1) * 128 + c0];
            #pragma unroll
            for (int ei = 0; ei < 8; ei++) {
                ulonglong2 h2 = *(const ulonglong2*)&sdup[ei * 32 + j];
                a1[ei][0] = ffma2(h2.x, wA.x, a1[ei][0]);
                a1[ei][1] = ffma2(h2.x, wA.y, a1[ei][1]);
                a1[ei][0] = ffma2(h2.y, wB.x, a1[ei][0]);
                a1[ei][1] = ffma2(h2.y, wB.y, a1[ei][1]);
            }
        }
        __syncwarp();

        // write e1 duplicated into sdup (rbf no longer needed)
        #pragma unroll
        for (int ei = 0; ei < 8; ei++)
            sdup[ei * 32 + lane] = pack2(e1r[ei], e1r[ei]);

        // silu + duplicate h1 into h1dup
        #pragma unroll
        for (int ei = 0; ei < 8; ei++) {
            float x0, x1, x2, x3;
            unpack2(a1[ei][0], x0, x1);
            unpack2(a1[ei][1], x2, x3);
            float h0 = silu_f(x0), h1v = silu_f(x1);
            float h2v = silu_f(x2), h3v = silu_f(x3);
            ulonglong2 s0, s1;
            s0.x = pack2(h0, h0);   s0.y = pack2(h1v, h1v);
            s1.x = pack2(h2v, h2v); s1.y = pack2(h3v, h3v);
            *(ulonglong2*)&h1dup[ei * 128 + c0]     = s0;
            *(ulonglong2*)&h1dup[ei * 128 + c0 + 2] = s1;
        }
        __syncwarp();

        // stage 2: h2pre = h1 @ wr2 + br2   (K=128)
        u64 a2[8][2];
        #pragma unroll
        for (int ei = 0; ei < 8; ei++) {
            a2[ei][0] = pack2(br2v.x, br2v.y);
            a2[ei][1] = pack2(br2v.z, br2v.w);
        }
        #pragma unroll 4
        for (int j = 0; j < 128; j += 2) {
            ulonglong2 wA = *(const ulonglong2*)&wr2s[j * 128 + c0];
            ulonglong2 wB = *(const ulonglong2*)&wr2s[(j + 1) * 128 + c0];
            #pragma unroll
            for (int ei = 0; ei < 8; ei++) {
                ulonglong2 h2 = *(const ulonglong2*)&h1dup[ei * 128 + j];
                a2[ei][0] = ffma2(h2.x, wA.x, a2[ei][0]);
                a2[ei][1] = ffma2(h2.x, wA.y, a2[ei][1]);
                a2[ei][0] = ffma2(h2.y, wB.x, a2[ei][0]);
                a2[ei][1] = ffma2(h2.y, wB.y, a2[ei][1]);
            }
        }

        // silu(stage2) into floats
        float o2[8][4];
        #pragma unroll
        for (int ei = 0; ei < 8; ei++) {
            float x0, x1, x2, x3;
            unpack2(a2[ei][0], x0, x1);
            unpack2(a2[ei][1], x2, x3);
            o2[ei][0] = silu_f(x0); o2[ei][1] = silu_f(x1);
            o2[ei][2] = silu_f(x2); o2[ei][3] = silu_f(x3);
        }

        // stage E: e2pre = e1 @ we2 + be2   (K=32)
        u64 aE[8][2];
        #pragma unroll
        for (int ei = 0; ei < 8; ei++) {
            aE[ei][0] = pack2(be2v.x, be2v.y);
            aE[ei][1] = pack2(be2v.z, be2v.w);
        }
        #pragma unroll 4
        for (int j = 0; j < 32; j += 2) {
            ulonglong2 wA = *(const ulonglong2*)&we2s[j * 128 + c0];
            ulonglong2 wB = *(const ulonglong2*)&we2s[(j + 1) * 128 + c0];
            #pragma unroll
            for (int ei = 0; ei < 8; ei++) {
                ulonglong2 h2 = *(const ulonglong2*)&sdup[ei * 32 + j];
                aE[ei][0] = ffma2(h2.x, wA.x, aE[ei][0]);
                aE[ei][1] = ffma2(h2.x, wA.y, aE[ei][1]);
                aE[ei][0] = ffma2(h2.y, wB.x, aE[ei][0]);
                aE[ei][1] = ffma2(h2.y, wB.y, aE[ei][1]);
            }
        }

        // out = silu(stage2) + silu(stageE)
        #pragma unroll
        for (int ei = 0; ei < 8; ei++) {
            int e = ebase + ei;
            if (e < E) {
                float y0, y1, y2, y3;
                unpack2(aE[ei][0], y0, y1);
                unpack2(aE[ei][1], y2, y3);
                float4 o;
                o.x = o2[ei][0] + silu_f(y0);
                o.y = o2[ei][1] + silu_f(y1);
                o.z = o2[ei][2] + silu_f(y2);
                o.w = o2[ei][3] + silu_f(y3);
                *(float4*)&outw[(size_t)e * 128 + c0] = o;
            }
        }
        __syncwarp();
    }
}

// ---------------------------------------------------------------------------
// Node kernel (unchanged from round 1): 134us, ~5% of total.
// ---------------------------------------------------------------------------
__global__ __launch_bounds__(264, 2)
void node_kernel(const float* __restrict__ inv_f, const float* __restrict__ ev_f,
                 const float* __restrict__ w_int, const float* __restrict__ b_int,
                 float* __restrict__ out_inv, float* __restrict__ out_ev, int N)
{
    extern __shared__ float sm[];
    float* Wsh = sm;                 // 132*132 = 17424
    float* bsh = Wsh + 17424;        // 132
    float* xs  = bsh + 132;          // 32*132 = 4224
    float* aev = xs + 4224;          // 32*16  = 512

    const int tx  = threadIdx.x;     // 0..32
    const int ty  = threadIdx.y;     // 0..7
    const int tid = tx + 33 * ty;
    const int NT  = 264;

    for (int i = tid; i < 17424; i += NT) Wsh[i] = w_int[i];
    if (tid < 132) bsh[tid] = b_int[tid];
    __syncthreads();

    const int nTiles = (N + 31) / 32;
    for (int tile = blockIdx.x; tile < nTiles; tile += gridDim.x) {
        const int base = tile * 32;

        for (int i = tid; i < 32 * 132; i += NT) {
            int l = i / 132, c = i % 132;
            int n = base + l;
            float v = 0.0f;
            if (n < N) {
                if (c < 128) {
                    v = 2.0f * inv_f[(size_t)n * 128 + c];
                } else {
                    const int st[5] = {0, 1, 4, 9, 16};
                    int s = c - 128;
                    float acc = 0.0f;
                    for (int k = st[s]; k < st[s + 1]; k++) {
                        float a = 2.0f * ev_f[(size_t)n * 16 + k];
                        acc = fmaf(a, a, acc);
                    }
                    v = acc;
                }
            }
            xs[l * 132 + c] = v;
        }
        for (int i = tid; i < 512; i += NT) {
            int l = i / 16, k = i % 16;
            int n = base + l;
            aev[i] = (n < N) ? 2.0f * ev_f[(size_t)n * 16 + k] : 0.0f;
        }
        __syncthreads();

        const int c0 = tx * 4;
        float acc[4][4];
        #pragma unroll
        for (int i = 0; i < 4; i++)
            #pragma unroll
            for (int k = 0; k < 4; k++) acc[i][k] = 0.0f;

        #pragma unroll 4
        for (int j = 0; j < 132; j++) {
            float4 w4 = *(const float4*)&Wsh[j * 132 + c0];
            #pragma unroll
            for (int i = 0; i < 4; i++) {
                float xv = xs[(ty * 4 + i) * 132 + j];
                acc[i][0] = fmaf(xv, w4.x, acc[i][0]);
                acc[i][1] = fmaf(xv, w4.y, acc[i][1]);
                acc[i][2] = fmaf(xv, w4.z, acc[i][2]);
                acc[i][3] = fmaf(xv, w4.w, acc[i][3]);
            }
        }

        const float4 bv = *(const float4*)&bsh[c0];
        #pragma unroll
        for (int i = 0; i < 4; i++) {
            int n = base + ty * 4 + i;
            if (n >= N) continue;
            float t0 = acc[i][0] + bv.x;
            float t1 = acc[i][1] + bv.y;
            float t2 = acc[i][2] + bv.z;
            float t3 = acc[i][3] + bv.w;
            if (tx < 32) {
                float4 o;
                o.x = xs[(ty * 4 + i) * 132 + c0 + 0] + t0;
                o.y = xs[(ty * 4 + i) * 132 + c0 + 1] + t1;
                o.z = xs[(ty * 4 + i) * 132 + c0 + 2] + t2;
                o.w = xs[(ty * 4 + i) * 132 + c0 + 3] + t3;
                *(float4*)&out_inv[(size_t)n * 128 + c0] = o;
            } else {
                float tb[4] = {t0, t1, t2, t3};
                const int SEG[16] = {0,1,1,1,2,2,2,2,2,3,3,3,3,3,3,3};
                #pragma unroll
                for (int k = 0; k < 16; k++) {
                    out_ev[(size_t)n * 16 + k] =
                        aev[(ty * 4 + i) * 16 + k] * (1.0f + tb[SEG[k]]);
                }
            }
        }
        __syncthreads();
    }
}

// ---------------------------------------------------------------------------
// Launch
// ---------------------------------------------------------------------------
static const int EDGE_SMEM = 100480 + 12 * 1280 * 8;   // 100480 + 122880 = 223360 B
static const int NODE_SMEM = 22292 * 4;                // 89168 B

extern "C" void kernel_launch(void* const* d_in, const int* in_sizes, int n_in,
                              void* d_out, int out_size)
{
    const float* inv_f     = (const float*)d_in[0];
    const float* ev_f      = (const float*)d_in[1];
    const int*   senders   = (const int*)  d_in[2];
    const int*   receivers = (const int*)  d_in[3];
    const float* lengths   = (const float*)d_in[5];

    const float* fi_rbf_w1 = (const float*)d_in[7];
    const float* fi_rbf_b1 = (const float*)d_in[8];
    const float* fi_rbf_w2 = (const float*)d_in[9];
    const float* fi_rbf_b2 = (const float*)d_in[10];
    const float* fi_ev_w1  = (const float*)d_in[11];
    const float* fi_ev_b1  = (const float*)d_in[12];
    const float* fi_ev_w2  = (const float*)d_in[13];
    const float* fi_ev_b2  = (const float*)d_in[14];
    const float* fe_rbf_w1 = (const float*)d_in[15];
    const float* fe_rbf_b1 = (const float*)d_in[16];
    const float* fe_rbf_w2 = (const float*)d_in[17];
    const float* fe_rbf_b2 = (const float*)d_in[18];
    const float* fe_ev_w1  = (const float*)d_in[19];
    const float* fe_ev_b1  = (const float*)d_in[20];
    const float* fe_ev_w2  = (const float*)d_in[21];
    const float* fe_ev_b2  = (const float*)d_in[22];
    const float* w_int     = (const float*)d_in[23];
    const float* b_int     = (const float*)d_in[24];

    const int N = in_sizes[0] / 128;
    const int E = in_sizes[2];

    float* out     = (float*)d_out;
    float* out_inv = out;
    float* out_ev  = out + (size_t)N * 128;
    float* fw_inv  = out + (size_t)N * 144;
    float* fw_ev   = fw_inv + (size_t)E * 128;

    cudaFuncSetAttribute(node_kernel,
                         cudaFuncAttributeMaxDynamicSharedMemorySize, NODE_SMEM);
    cudaFuncSetAttribute(edge_filter_kernel,
                         cudaFuncAttributeMaxDynamicSharedMemorySize, EDGE_SMEM);

    node_kernel<<<304, dim3(33, 8), NODE_SMEM>>>(
        inv_f, ev_f, w_int, b_int, out_inv, out_ev, N);

    edge_filter_kernel<<<148, 384, EDGE_SMEM>>>(
        ev_f, senders, receivers, lengths,
        fi_rbf_w1, fi_rbf_b1, fi_rbf_w2, fi_rbf_b2,
        fi_ev_w1,  fi_ev_b1,  fi_ev_w2,  fi_ev_b2,
        fw_inv, E);

    edge_filter_kernel<<<148, 384, EDGE_SMEM>>>(
        ev_f, senders, receivers, lengths,
        fe_rbf_w1, fe_rbf_b1, fe_rbf_w2, fe_rbf_b2,
        fe_ev_w1,  fe_ev_b1,  fe_ev_w2,  fe_ev_b2,
        fw_ev, E);
}

// round 5
// speedup vs baseline: 1.3186x; 1.3186x over previous
#include <cuda_runtime.h>
#include <cuda_bf16.h>

typedef unsigned int u32;
#define FULLMASK 0xffffffffu

__device__ __forceinline__ float silu_f(float x){ return x / (1.0f + __expf(-x)); }

__device__ __forceinline__ void bsplit(float x, __nv_bfloat16& h, __nv_bfloat16& l){
    h = __float2bfloat16(x);
    l = __float2bfloat16(x - __bfloat162float(h));
}
__device__ __forceinline__ u32 bpack(__nv_bfloat16 a, __nv_bfloat16 b){
    return (u32)__bfloat16_as_ushort(a) | ((u32)__bfloat16_as_ushort(b) << 16);
}
// split two floats directly into packed hi / packed lo u32s
__device__ __forceinline__ void bsplit2(float x0, float x1, u32& hi, u32& lo){
    __nv_bfloat16 h0, l0, h1, l1;
    bsplit(x0, h0, l0); bsplit(x1, h1, l1);
    hi = bpack(h0, h1); lo = bpack(l0, l1);
}

__device__ __forceinline__ void mma16816(float c[4], const u32 a[4], u32 b0, u32 b1){
    asm volatile(
        "mma.sync.aligned.m16n8k16.row.col.f32.bf16.bf16.f32 "
        "{%0,%1,%2,%3}, {%4,%5,%6,%7}, {%8,%9}, {%0,%1,%2,%3};"
        : "+f"(c[0]), "+f"(c[1]), "+f"(c[2]), "+f"(c[3])
        : "r"(a[0]), "r"(a[1]), "r"(a[2]), "r"(a[3]), "r"(b0), "r"(b1));
}

// ---------------- smem layout (bytes) ----------------
// weights transposed [n][k] as bf16, hi/lo split.
// pitch 72B for k=32 rows, 272B for k=128 rows (bank-conflict-free u32 frags)
#define PW1 72
#define PW2 272
#define O_W1H 0u
#define O_W1L 9216u
#define O_WEH 18432u
#define O_WEL 27648u
#define O_W2H 36864u
#define O_W2L 71680u
#define O_BR1 106496u
#define O_BR2 107008u
#define O_BE2 107520u
#define O_BE1 108032u
#define O_WE1 108160u
#define O_WARP 108672u
#define WARP_SZ 9024u          // A2H 4352 + A2L 4352 + invw 256 + lenw 64
#define EDGE_SMEM (108672 + 8 * 9024)   // 180864

__global__ __launch_bounds__(256, 1)
void edge_filter_mma(const float* __restrict__ evf,
                     const int*   __restrict__ senders,
                     const int*   __restrict__ receivers,
                     const float* __restrict__ lengths,
                     const float* __restrict__ wr1, const float* __restrict__ br1,
                     const float* __restrict__ wr2, const float* __restrict__ br2,
                     const float* __restrict__ we1, const float* __restrict__ be1,
                     const float* __restrict__ we2, const float* __restrict__ be2,
                     float* __restrict__ outw, int E)
{
    extern __shared__ char smc[];
    const int tid  = threadIdx.x;
    const int lane = tid & 31;
    const int warp = tid >> 5;

    // ---- preload weights (transposed + split) ----
    for (int i = tid; i < 4096; i += 256) {          // wr1 [32k][128n]
        int n = i & 127, k = i >> 7;
        __nv_bfloat16 h, l; bsplit(wr1[k * 128 + n], h, l);
        *(__nv_bfloat16*)(smc + O_W1H + n * PW1 + k * 2) = h;
        *(__nv_bfloat16*)(smc + O_W1L + n * PW1 + k * 2) = l;
    }
    for (int i = tid; i < 4096; i += 256) {          // we2 [32k][128n]
        int n = i & 127, k = i >> 7;
        __nv_bfloat16 h, l; bsplit(we2[k * 128 + n], h, l);
        *(__nv_bfloat16*)(smc + O_WEH + n * PW1 + k * 2) = h;
        *(__nv_bfloat16*)(smc + O_WEL + n * PW1 + k * 2) = l;
    }
    for (int i = tid; i < 16384; i += 256) {         // wr2 [128k][128n]
        int n = i & 127, k = i >> 7;
        __nv_bfloat16 h, l; bsplit(wr2[k * 128 + n], h, l);
        *(__nv_bfloat16*)(smc + O_W2H + n * PW2 + k * 2) = h;
        *(__nv_bfloat16*)(smc + O_W2L + n * PW2 + k * 2) = l;
    }
    float* br1s = (float*)(smc + O_BR1);
    float* br2s = (float*)(smc + O_BR2);
    float* be2s = (float*)(smc + O_BE2);
    float* be1s = (float*)(smc + O_BE1);
    float* we1s = (float*)(smc + O_WE1);
    if (tid < 128) { br1s[tid] = br1[tid]; br2s[tid] = br2[tid];
                     be2s[tid] = be2[tid]; we1s[tid] = we1[tid]; }
    if (tid < 32)  be1s[tid] = be1[tid];
    __syncthreads();

    char* wbase = smc + O_WARP + warp * WARP_SZ;
    char* A2H   = wbase;
    char* A2L   = wbase + 4352;
    float* invw = (float*)(wbase + 8704);   // [16][4]
    float* lenw = (float*)(wbase + 8960);   // [16]

    const int qk   = lane & 3;          // k-pair index within frag
    const int rr   = lane >> 2;         // row-in-tile 0..7
    const float STEP = 5.0f / 31.0f;
    const float GAMMA = 0.5f * (31.0f / 5.0f) * (31.0f / 5.0f);

    const int nGroups = (E + 15) >> 4;
    const int gstride = gridDim.x * 8;

    for (int g = blockIdx.x * 8 + warp; g < nGroups; g += gstride) {
        const int ebase = g * 16;

        // ---- edge meta: senders/receivers/lengths ----
        int sI = 0, rI = 0;
        if (lane < 16) {
            int ge = ebase + lane; if (ge >= E) ge = E - 1;
            sI = senders[ge]; rI = receivers[ge];
            lenw[lane] = lengths[ge];
        }
        // invariants: 2 lanes per edge
        {
            int m = lane >> 1, half = lane & 1;
            int sm_ = __shfl_sync(FULLMASK, sI, m);
            int rm_ = __shfl_sync(FULLMASK, rI, m);
            const float4* ps = (const float4*)(evf + (size_t)sm_ * 16 + half * 8);
            const float4* pr = (const float4*)(evf + (size_t)rm_ * 16 + half * 8);
            float4 sa = ps[0], sb = ps[1], ra = pr[0], rb = pr[1];
            float d[8];
            d[0] = sa.x - ra.x; d[1] = sa.y - ra.y; d[2] = sa.z - ra.z; d[3] = sa.w - ra.w;
            d[4] = sb.x - rb.x; d[5] = sb.y - rb.y; d[6] = sb.z - rb.z; d[7] = sb.w - rb.w;
            #pragma unroll
            for (int i = 0; i < 8; i++) d[i] *= d[i];
            float q0, q1, q2p, q3p;
            if (half == 0) {
                q0 = d[0]; q1 = d[1] + d[2] + d[3];
                q2p = d[4] + d[5] + d[6] + d[7]; q3p = 0.0f;
            } else {
                q0 = 0.0f; q1 = 0.0f;
                q2p = d[0];
                q3p = d[1] + d[2] + d[3] + d[4] + d[5] + d[6] + d[7];
            }
            float q0f = q0 + __shfl_xor_sync(FULLMASK, q0, 1);
            float q1f = q1 + __shfl_xor_sync(FULLMASK, q1, 1);
            float q2f = q2p + __shfl_xor_sync(FULLMASK, q2p, 1);
            float q3f = q3p + __shfl_xor_sync(FULLMASK, q3p, 1);
            if (half == 0) {
                invw[m * 4 + 0] = q0f; invw[m * 4 + 1] = q1f;
                invw[m * 4 + 2] = q2f; invw[m * 4 + 3] = q3f;
            }
        }
        __syncwarp();

        // ============ stage 1: h1pre = rbf @ wr1 ============
        float C1[16][4];
        #pragma unroll
        for (int nf = 0; nf < 16; nf++)
            { C1[nf][0] = 0.f; C1[nf][1] = 0.f; C1[nf][2] = 0.f; C1[nf][3] = 0.f; }

        const float lm0 = lenw[rr], lm8 = lenw[rr + 8];
        #pragma unroll
        for (int ks = 0; ks < 2; ks++) {
            const int kb = 2 * qk + 16 * ks;
            float c0 = (float)kb * STEP, c1 = (float)(kb + 1) * STEP;
            float c8 = (float)(kb + 8) * STEP, c9 = (float)(kb + 9) * STEP;
            float t;
            u32 ah[4], al[4];
            t = lm0 - c0; float v0 = __expf(-GAMMA * t * t);
            t = lm0 - c1; float v1 = __expf(-GAMMA * t * t);
            t = lm8 - c0; float v2 = __expf(-GAMMA * t * t);
            t = lm8 - c1; float v3 = __expf(-GAMMA * t * t);
            t = lm0 - c8; float v4 = __expf(-GAMMA * t * t);
            t = lm0 - c9; float v5 = __expf(-GAMMA * t * t);
            t = lm8 - c8; float v6 = __expf(-GAMMA * t * t);
            t = lm8 - c9; float v7 = __expf(-GAMMA * t * t);
            bsplit2(v0, v1, ah[0], al[0]); bsplit2(v2, v3, ah[1], al[1]);
            bsplit2(v4, v5, ah[2], al[2]); bsplit2(v6, v7, ah[3], al[3]);
            #pragma unroll
            for (int nf = 0; nf < 16; nf++) {
                u32 off = (u32)((nf * 8 + rr) * PW1 + (2 * qk + 16 * ks) * 2);
                u32 bh0 = *(const u32*)(smc + O_W1H + off);
                u32 bh1 = *(const u32*)(smc + O_W1H + off + 16);
                u32 bl0 = *(const u32*)(smc + O_W1L + off);
                u32 bl1 = *(const u32*)(smc + O_W1L + off + 16);
                mma16816(C1[nf], ah, bh0, bh1);
                mma16816(C1[nf], al, bh0, bh1);
                mma16816(C1[nf], ah, bl0, bl1);
            }
        }
        // silu + split -> A2 (h1 as stage-2 A operand)
        #pragma unroll
        for (int nf = 0; nf < 16; nf++) {
            int c = nf * 8 + 2 * qk;
            float2 b1v = *(const float2*)&br1s[c];
            u32 hi, lo;
            bsplit2(silu_f(C1[nf][0] + b1v.x), silu_f(C1[nf][1] + b1v.y), hi, lo);
            *(u32*)(A2H + rr * PW2 + c * 2) = hi;
            *(u32*)(A2L + rr * PW2 + c * 2) = lo;
            bsplit2(silu_f(C1[nf][2] + b1v.x), silu_f(C1[nf][3] + b1v.y), hi, lo);
            *(u32*)(A2H + (rr + 8) * PW2 + c * 2) = hi;
            *(u32*)(A2L + (rr + 8) * PW2 + c * 2) = lo;
        }
        __syncwarp();

        // ============ stage E: e2pre = e1 @ we2 ============
        float CE[16][4];
        #pragma unroll
        for (int nf = 0; nf < 16; nf++)
            { CE[nf][0] = 0.f; CE[nf][1] = 0.f; CE[nf][2] = 0.f; CE[nf][3] = 0.f; }

        float i0q[4], i8q[4];
        #pragma unroll
        for (int q = 0; q < 4; q++) { i0q[q] = invw[rr * 4 + q]; i8q[q] = invw[(rr + 8) * 4 + q]; }

        #pragma unroll
        for (int ks = 0; ks < 2; ks++) {
            const int kb = 2 * qk + 16 * ks;
            u32 ah[4], al[4];
            float ev[8];
            const int kk[4] = {kb, kb + 1, kb + 8, kb + 9};
            #pragma unroll
            for (int j = 0; j < 4; j++) {
                int k = kk[j];
                float w0 = we1s[k], w1 = we1s[32 + k], w2 = we1s[64 + k], w3 = we1s[96 + k];
                float bk = be1s[k];
                float a0 = bk, a8 = bk;
                a0 = fmaf(i0q[0], w0, a0); a0 = fmaf(i0q[1], w1, a0);
                a0 = fmaf(i0q[2], w2, a0); a0 = fmaf(i0q[3], w3, a0);
                a8 = fmaf(i8q[0], w0, a8); a8 = fmaf(i8q[1], w1, a8);
                a8 = fmaf(i8q[2], w2, a8); a8 = fmaf(i8q[3], w3, a8);
                ev[j * 2]     = silu_f(a0);
                ev[j * 2 + 1] = silu_f(a8);
            }
            // ev: [k][m-half]: build frags (v(m,kb),v(m,kb+1))...
            bsplit2(ev[0], ev[2], ah[0], al[0]);   // (r, kb), (r, kb+1)
            bsplit2(ev[1], ev[3], ah[1], al[1]);   // (r+8, kb), (r+8, kb+1)
            bsplit2(ev[4], ev[6], ah[2], al[2]);   // (r, kb+8), (r, kb+9)
            bsplit2(ev[5], ev[7], ah[3], al[3]);   // (r+8, kb+8), (r+8, kb+9)
            #pragma unroll
            for (int nf = 0; nf < 16; nf++) {
                u32 off = (u32)((nf * 8 + rr) * PW1 + (2 * qk + 16 * ks) * 2);
                u32 bh0 = *(const u32*)(smc + O_WEH + off);
                u32 bh1 = *(const u32*)(smc + O_WEH + off + 16);
                u32 bl0 = *(const u32*)(smc + O_WEL + off);
                u32 bl1 = *(const u32*)(smc + O_WEL + off + 16);
                mma16816(CE[nf], ah, bh0, bh1);
                mma16816(CE[nf], al, bh0, bh1);
                mma16816(CE[nf], ah, bl0, bl1);
            }
        }

        // ============ stage 2: h2pre = h1 @ wr2 ============
        float C2[16][4];
        #pragma unroll
        for (int nf = 0; nf < 16; nf++)
            { C2[nf][0] = 0.f; C2[nf][1] = 0.f; C2[nf][2] = 0.f; C2[nf][3] = 0.f; }

        #pragma unroll
        for (int ks = 0; ks < 8; ks++) {
            u32 aoff = (u32)(rr * PW2 + (2 * qk + 16 * ks) * 2);
            u32 ah[4], al[4];
            ah[0] = *(const u32*)(A2H + aoff);
            ah[1] = *(const u32*)(A2H + aoff + 8 * PW2);
            ah[2] = *(const u32*)(A2H + aoff + 16);
            ah[3] = *(const u32*)(A2H + aoff + 8 * PW2 + 16);
            al[0] = *(const u32*)(A2L + aoff);
            al[1] = *(const u32*)(A2L + aoff + 8 * PW2);
            al[2] = *(const u32*)(A2L + aoff + 16);
            al[3] = *(const u32*)(A2L + aoff + 8 * PW2 + 16);
            #pragma unroll
            for (int nf = 0; nf < 16; nf++) {
                u32 off = (u32)((nf * 8 + rr) * PW2 + (2 * qk + 16 * ks) * 2);
                u32 bh0 = *(const u32*)(smc + O_W2H + off);
                u32 bh1 = *(const u32*)(smc + O_W2H + off + 16);
                u32 bl0 = *(const u32*)(smc + O_W2L + off);
                u32 bl1 = *(const u32*)(smc + O_W2L + off + 16);
                mma16816(C2[nf], ah, bh0, bh1);
                mma16816(C2[nf], al, bh0, bh1);
                mma16816(C2[nf], ah, bl0, bl1);
            }
        }

        // ============ epilogue ============
        const int e0 = ebase + rr, e1_ = ebase + rr + 8;
        float* p0 = outw + (size_t)e0 * 128;
        float* p1 = outw + (size_t)e1_ * 128;
        #pragma unroll
        for (int nf = 0; nf < 16; nf++) {
            int c = nf * 8 + 2 * qk;
            float2 b2 = *(const float2*)&br2s[c];
            float2 be = *(const float2*)&be2s[c];
            if (e0 < E) {
                float2 o;
                o.x = silu_f(C2[nf][0] + b2.x) + silu_f(CE[nf][0] + be.x);
                o.y = silu_f(C2[nf][1] + b2.y) + silu_f(CE[nf][1] + be.y);
                *(float2*)&p0[c] = o;
            }
            if (e1_ < E) {
                float2 o;
                o.x = silu_f(C2[nf][2] + b2.x) + silu_f(CE[nf][2] + be.x);
                o.y = silu_f(C2[nf][3] + b2.y) + silu_f(CE[nf][3] + be.y);
                *(float2*)&p1[c] = o;
            }
        }
        __syncwarp();
    }
}

// ---------------------------------------------------------------------------
// Node kernel (unchanged, ~134us)
// ---------------------------------------------------------------------------
__global__ __launch_bounds__(264, 2)
void node_kernel(const float* __restrict__ inv_f, const float* __restrict__ ev_f,
                 const float* __restrict__ w_int, const float* __restrict__ b_int,
                 float* __restrict__ out_inv, float* __restrict__ out_ev, int N)
{
    extern __shared__ float sm[];
    float* Wsh = sm;
    float* bsh = Wsh + 17424;
    float* xs  = bsh + 132;
    float* aev = xs + 4224;

    const int tx  = threadIdx.x;
    const int ty  = threadIdx.y;
    const int tid = tx + 33 * ty;
    const int NT  = 264;

    for (int i = tid; i < 17424; i += NT) Wsh[i] = w_int[i];
    if (tid < 132) bsh[tid] = b_int[tid];
    __syncthreads();

    const int nTiles = (N + 31) / 32;
    for (int tile = blockIdx.x; tile < nTiles; tile += gridDim.x) {
        const int base = tile * 32;

        for (int i = tid; i < 32 * 132; i += NT) {
            int l = i / 132, c = i % 132;
            int n = base + l;
            float v = 0.0f;
            if (n < N) {
                if (c < 128) {
                    v = 2.0f * inv_f[(size_t)n * 128 + c];
                } else {
                    const int st[5] = {0, 1, 4, 9, 16};
                    int s = c - 128;
                    float acc = 0.0f;
                    for (int k = st[s]; k < st[s + 1]; k++) {
                        float a = 2.0f * ev_f[(size_t)n * 16 + k];
                        acc = fmaf(a, a, acc);
                    }
                    v = acc;
                }
            }
            xs[l * 132 + c] = v;
        }
        for (int i = tid; i < 512; i += NT) {
            int l = i / 16, k = i % 16;
            int n = base + l;
            aev[i] = (n < N) ? 2.0f * ev_f[(size_t)n * 16 + k] : 0.0f;
        }
        __syncthreads();

        const int c0 = tx * 4;
        float acc[4][4];
        #pragma unroll
        for (int i = 0; i < 4; i++)
            #pragma unroll
            for (int k = 0; k < 4; k++) acc[i][k] = 0.0f;

        #pragma unroll 4
        for (int j = 0; j < 132; j++) {
            float4 w4 = *(const float4*)&Wsh[j * 132 + c0];
            #pragma unroll
            for (int i = 0; i < 4; i++) {
                float xv = xs[(ty * 4 + i) * 132 + j];
                acc[i][0] = fmaf(xv, w4.x, acc[i][0]);
                acc[i][1] = fmaf(xv, w4.y, acc[i][1]);
                acc[i][2] = fmaf(xv, w4.z, acc[i][2]);
                acc[i][3] = fmaf(xv, w4.w, acc[i][3]);
            }
        }

        const float4 bv = *(const float4*)&bsh[c0];
        #pragma unroll
        for (int i = 0; i < 4; i++) {
            int n = base + ty * 4 + i;
            if (n >= N) continue;
            float t0 = acc[i][0] + bv.x;
            float t1 = acc[i][1] + bv.y;
            float t2 = acc[i][2] + bv.z;
            float t3 = acc[i][3] + bv.w;
            if (tx < 32) {
                float4 o;
                o.x = xs[(ty * 4 + i) * 132 + c0 + 0] + t0;
                o.y = xs[(ty * 4 + i) * 132 + c0 + 1] + t1;
                o.z = xs[(ty * 4 + i) * 132 + c0 + 2] + t2;
                o.w = xs[(ty * 4 + i) * 132 + c0 + 3] + t3;
                *(float4*)&out_inv[(size_t)n * 128 + c0] = o;
            } else {
                float tb[4] = {t0, t1, t2, t3};
                const int SEG[16] = {0,1,1,1,2,2,2,2,2,3,3,3,3,3,3,3};
                #pragma unroll
                for (int k = 0; k < 16; k++) {
                    out_ev[(size_t)n * 16 + k] =
                        aev[(ty * 4 + i) * 16 + k] * (1.0f + tb[SEG[k]]);
                }
            }
        }
        __syncthreads();
    }
}

static const int NODE_SMEM = 22292 * 4;

extern "C" void kernel_launch(void* const* d_in, const int* in_sizes, int n_in,
                              void* d_out, int out_size)
{
    const float* inv_f     = (const float*)d_in[0];
    const float* ev_f      = (const float*)d_in[1];
    const int*   senders   = (const int*)  d_in[2];
    const int*   receivers = (const int*)  d_in[3];
    const float* lengths   = (const float*)d_in[5];

    const float* fi_rbf_w1 = (const float*)d_in[7];
    const float* fi_rbf_b1 = (const float*)d_in[8];
    const float* fi_rbf_w2 = (const float*)d_in[9];
    const float* fi_rbf_b2 = (const float*)d_in[10];
    const float* fi_ev_w1  = (const float*)d_in[11];
    const float* fi_ev_b1  = (const float*)d_in[12];
    const float* fi_ev_w2  = (const float*)d_in[13];
    const float* fi_ev_b2  = (const float*)d_in[14];
    const float* fe_rbf_w1 = (const float*)d_in[15];
    const float* fe_rbf_b1 = (const float*)d_in[16];
    const float* fe_rbf_w2 = (const float*)d_in[17];
    const float* fe_rbf_b2 = (const float*)d_in[18];
    const float* fe_ev_w1  = (const float*)d_in[19];
    const float* fe_ev_b1  = (const float*)d_in[20];
    const float* fe_ev_w2  = (const float*)d_in[21];
    const float* fe_ev_b2  = (const float*)d_in[22];
    const float* w_int     = (const float*)d_in[23];
    const float* b_int     = (const float*)d_in[24];

    const int N = in_sizes[0] / 128;
    const int E = in_sizes[2];

    float* out     = (float*)d_out;
    float* out_inv = out;
    float* out_ev  = out + (size_t)N * 128;
    float* fw_inv  = out + (size_t)N * 144;
    float* fw_ev   = fw_inv + (size_t)E * 128;

    cudaFuncSetAttribute(node_kernel,
                         cudaFuncAttributeMaxDynamicSharedMemorySize, NODE_SMEM);
    cudaFuncSetAttribute(edge_filter_mma,
                         cudaFuncAttributeMaxDynamicSharedMemorySize, EDGE_SMEM);

    edge_filter_mma<<<148, 256, EDGE_SMEM>>>(
        ev_f, senders, receivers, lengths,
        fi_rbf_w1, fi_rbf_b1, fi_rbf_w2, fi_rbf_b2,
        fi_ev_w1,  fi_ev_b1,  fi_ev_w2,  fi_ev_b2,
        fw_inv, E);

    edge_filter_mma<<<148, 256, EDGE_SMEM>>>(
        ev_f, senders, receivers, lengths,
        fe_rbf_w1, fe_rbf_b1, fe_rbf_w2, fe_rbf_b2,
        fe_ev_w1,  fe_ev_b1,  fe_ev_w2,  fe_ev_b2,
        fw_ev, E);

    node_kernel<<<304, dim3(33, 8), NODE_SMEM>>>(
        inv_f, ev_f, w_int, b_int, out_inv, out_ev, N);
}

// round 8
// speedup vs baseline: 1.5748x; 1.1943x over previous
#include <cuda_runtime.h>
#include <cuda_bf16.h>

typedef unsigned int u32;
#define FULLMASK 0xffffffffu

__device__ __forceinline__ float silu_f(float x){ return x / (1.0f + __expf(-x)); }

__device__ __forceinline__ u32 smem_u32(const void* p){
    u32 a;
    asm("{ .reg .u64 t; cvta.to.shared.u64 t, %1; cvt.u32.u64 %0, t; }" : "=r"(a) : "l"(p));
    return a;
}
__device__ __forceinline__ void bsplit(float x, __nv_bfloat16& h, __nv_bfloat16& l){
    h = __float2bfloat16(x);
    l = __float2bfloat16(x - __bfloat162float(h));
}
__device__ __forceinline__ u32 bpack(__nv_bfloat16 a, __nv_bfloat16 b){
    return (u32)__bfloat16_as_ushort(a) | ((u32)__bfloat16_as_ushort(b) << 16);
}
__device__ __forceinline__ void bsplit2(float x0, float x1, u32& hi, u32& lo){
    __nv_bfloat16 h0, l0, h1, l1;
    bsplit(x0, h0, l0); bsplit(x1, h1, l1);
    hi = bpack(h0, h1); lo = bpack(l0, l1);
}
__device__ __forceinline__ void mma16816(float c[4], const u32 a[4], u32 b0, u32 b1){
    asm volatile(
        "mma.sync.aligned.m16n8k16.row.col.f32.bf16.bf16.f32 "
        "{%0,%1,%2,%3}, {%4,%5,%6,%7}, {%8,%9}, {%0,%1,%2,%3};"
        : "+f"(c[0]), "+f"(c[1]), "+f"(c[2]), "+f"(c[3])
        : "r"(a[0]), "r"(a[1]), "r"(a[2]), "r"(a[3]), "r"(b0), "r"(b1));
}
__device__ __forceinline__ void ldsm4(u32 r[4], u32 saddr){
    asm volatile("ldmatrix.sync.aligned.m8n8.x4.shared.b16 {%0,%1,%2,%3}, [%4];"
        : "=r"(r[0]), "=r"(r[1]), "=r"(r[2]), "=r"(r[3]) : "r"(saddr));
}

// ---------------- smem layout (bytes) ----------------
// PW1 = 80: 16B-aligned rows for ldmatrix (trap fix), (5n)%8 spans all LDSM
// 16B-groups -> conflict-free. PW2 = 272 = 17*16 likewise.
#define PW1 80
#define PW2 272
#define O_W1H 0u          // 128*80 = 10240
#define O_W1L 10240u
#define O_WEH 20480u
#define O_WEL 30720u
#define O_W2H 40960u      // 128*272 = 34816
#define O_W2L 75776u
#define O_BR1 110592u
#define O_BR2 111104u
#define O_BE2 111616u
#define O_BE1 112128u
#define O_WE1 112256u
#define O_WARP 112768u
#define WARP_SZ 320u      // invw 256 + lenw 64
#define NWARPS 12
#define EDGE_SMEM (112768 + NWARPS * 320)   // 116608

__global__ __launch_bounds__(384, 1)
void edge_filter_mma(const float* __restrict__ evf,
                     const int*   __restrict__ senders,
                     const int*   __restrict__ receivers,
                     const float* __restrict__ lengths,
                     const float* __restrict__ wr1, const float* __restrict__ br1,
                     const float* __restrict__ wr2, const float* __restrict__ br2,
                     const float* __restrict__ we1, const float* __restrict__ be1,
                     const float* __restrict__ we2, const float* __restrict__ be2,
                     float* __restrict__ outw, int E)
{
    extern __shared__ char smc[];
    const u32 sbase = smem_u32(smc);
    const int tid  = threadIdx.x;
    const int lane = tid & 31;
    const int warp = tid >> 5;

    // ---- preload weights (transposed [n][k] + hi/lo split) ----
    for (int i = tid; i < 4096; i += 384) {          // wr1 [32k][128n]
        int n = i & 127, k = i >> 7;
        __nv_bfloat16 h, l; bsplit(wr1[k * 128 + n], h, l);
        *(__nv_bfloat16*)(smc + O_W1H + n * PW1 + k * 2) = h;
        *(__nv_bfloat16*)(smc + O_W1L + n * PW1 + k * 2) = l;
    }
    for (int i = tid; i < 4096; i += 384) {          // we2 [32k][128n]
        int n = i & 127, k = i >> 7;
        __nv_bfloat16 h, l; bsplit(we2[k * 128 + n], h, l);
        *(__nv_bfloat16*)(smc + O_WEH + n * PW1 + k * 2) = h;
        *(__nv_bfloat16*)(smc + O_WEL + n * PW1 + k * 2) = l;
    }
    for (int i = tid; i < 16384; i += 384) {         // wr2 [128k][128n]
        int n = i & 127, k = i >> 7;
        __nv_bfloat16 h, l; bsplit(wr2[k * 128 + n], h, l);
        *(__nv_bfloat16*)(smc + O_W2H + n * PW2 + k * 2) = h;
        *(__nv_bfloat16*)(smc + O_W2L + n * PW2 + k * 2) = l;
    }
    float* br1s = (float*)(smc + O_BR1);
    float* br2s = (float*)(smc + O_BR2);
    float* be2s = (float*)(smc + O_BE2);
    float* be1s = (float*)(smc + O_BE1);
    float* we1s = (float*)(smc + O_WE1);
    if (tid < 128) { br1s[tid] = br1[tid]; br2s[tid] = br2[tid];
                     be2s[tid] = be2[tid]; we1s[tid] = we1[tid]; }
    if (tid < 32)  be1s[tid] = be1[tid];
    __syncthreads();

    char* wbase = smc + O_WARP + warp * WARP_SZ;
    float* invw = (float*)(wbase);          // [16][4]
    float* lenw = (float*)(wbase + 256);    // [16]

    const int qk = lane & 3;
    const int rr = lane >> 2;
    const float STEP = 5.0f / 31.0f;
    const float GAMMA = 0.5f * (31.0f / 5.0f) * (31.0f / 5.0f);

    // ldmatrix lane-constant address parts
    const u32 lrow  = (u32)((lane & 7) + ((lane & 16) >> 1));
    const u32 lcolB = (u32)((lane & 8) << 1);
    const u32 bW1H = sbase + O_W1H + lrow * PW1 + lcolB;
    const u32 bW1L = sbase + O_W1L + lrow * PW1 + lcolB;
    const u32 bWEH = sbase + O_WEH + lrow * PW1 + lcolB;
    const u32 bWEL = sbase + O_WEL + lrow * PW1 + lcolB;
    const u32 bW2H = sbase + O_W2H + lrow * PW2 + lcolB;
    const u32 bW2L = sbase + O_W2L + lrow * PW2 + lcolB;

    const int nGroups = (E + 15) >> 4;
    const int gstride = gridDim.x * NWARPS;

    for (int g = blockIdx.x * NWARPS + warp; g < nGroups; g += gstride) {
        const int ebase = g * 16;

        // ---- edge meta ----
        int sI = 0, rI = 0;
        if (lane < 16) {
            int ge = ebase + lane; if (ge >= E) ge = E - 1;
            sI = senders[ge]; rI = receivers[ge];
            lenw[lane] = lengths[ge];
        }
        {   // invariants: 2 lanes per edge
            int m = lane >> 1, half = lane & 1;
            int sm_ = __shfl_sync(FULLMASK, sI, m);
            int rm_ = __shfl_sync(FULLMASK, rI, m);
            const float4* ps = (const float4*)(evf + (size_t)sm_ * 16 + half * 8);
            const float4* pr = (const float4*)(evf + (size_t)rm_ * 16 + half * 8);
            float4 sa = ps[0], sb = ps[1], ra = pr[0], rb = pr[1];
            float d[8];
            d[0] = sa.x - ra.x; d[1] = sa.y - ra.y; d[2] = sa.z - ra.z; d[3] = sa.w - ra.w;
            d[4] = sb.x - rb.x; d[5] = sb.y - rb.y; d[6] = sb.z - rb.z; d[7] = sb.w - rb.w;
            #pragma unroll
            for (int i = 0; i < 8; i++) d[i] *= d[i];
            float q0, q1, q2p, q3p;
            if (half == 0) {
                q0 = d[0]; q1 = d[1] + d[2] + d[3];
                q2p = d[4] + d[5] + d[6] + d[7]; q3p = 0.0f;
            } else {
                q0 = 0.0f; q1 = 0.0f; q2p = d[0];
                q3p = d[1] + d[2] + d[3] + d[4] + d[5] + d[6] + d[7];
            }
            float q0f = q0 + __shfl_xor_sync(FULLMASK, q0, 1);
            float q1f = q1 + __shfl_xor_sync(FULLMASK, q1, 1);
            float q2f = q2p + __shfl_xor_sync(FULLMASK, q2p, 1);
            float q3f = q3p + __shfl_xor_sync(FULLMASK, q3p, 1);
            if (half == 0) {
                invw[m * 4 + 0] = q0f; invw[m * 4 + 1] = q1f;
                invw[m * 4 + 2] = q2f; invw[m * 4 + 3] = q3f;
            }
        }
        __syncwarp();

        // ============ stage 1: h1pre = rbf @ wr1 ============
        float C1[16][4];
        #pragma unroll
        for (int nf = 0; nf < 16; nf++)
            { C1[nf][0] = 0.f; C1[nf][1] = 0.f; C1[nf][2] = 0.f; C1[nf][3] = 0.f; }

        const float lm0 = lenw[rr], lm8 = lenw[rr + 8];
        #pragma unroll
        for (int ks = 0; ks < 2; ks++) {
            const int kb = 2 * qk + 16 * ks;
            float c0 = (float)kb * STEP, c1 = (float)(kb + 1) * STEP;
            float c8 = (float)(kb + 8) * STEP, c9 = (float)(kb + 9) * STEP;
            float t;
            u32 ah[4], al[4];
            t = lm0 - c0; float v0 = __expf(-GAMMA * t * t);
            t = lm0 - c1; float v1 = __expf(-GAMMA * t * t);
            t = lm8 - c0; float v2 = __expf(-GAMMA * t * t);
            t = lm8 - c1; float v3 = __expf(-GAMMA * t * t);
            t = lm0 - c8; float v4 = __expf(-GAMMA * t * t);
            t = lm0 - c9; float v5 = __expf(-GAMMA * t * t);
            t = lm8 - c8; float v6 = __expf(-GAMMA * t * t);
            t = lm8 - c9; float v7 = __expf(-GAMMA * t * t);
            bsplit2(v0, v1, ah[0], al[0]); bsplit2(v2, v3, ah[1], al[1]);
            bsplit2(v4, v5, ah[2], al[2]); bsplit2(v6, v7, ah[3], al[3]);
            #pragma unroll
            for (int p = 0; p < 8; p++) {
                u32 bh[4], bl[4];
                ldsm4(bh, bW1H + (u32)(p * 16 * PW1 + ks * 32));
                ldsm4(bl, bW1L + (u32)(p * 16 * PW1 + ks * 32));
                mma16816(C1[2*p],   ah, bh[0], bh[1]);
                mma16816(C1[2*p],   al, bh[0], bh[1]);
                mma16816(C1[2*p],   ah, bl[0], bl[1]);
                mma16816(C1[2*p+1], ah, bh[2], bh[3]);
                mma16816(C1[2*p+1], al, bh[2], bh[3]);
                mma16816(C1[2*p+1], ah, bl[2], bl[3]);
            }
        }
        // h1 = silu(C1 + br1), kept in registers (C layout == A layout)
        #pragma unroll
        for (int nf = 0; nf < 16; nf++) {
            int c = nf * 8 + 2 * qk;
            float2 b1v = *(const float2*)&br1s[c];
            C1[nf][0] = silu_f(C1[nf][0] + b1v.x);
            C1[nf][1] = silu_f(C1[nf][1] + b1v.y);
            C1[nf][2] = silu_f(C1[nf][2] + b1v.x);
            C1[nf][3] = silu_f(C1[nf][3] + b1v.y);
        }

        // ============ stage 2: h2pre = h1 @ wr2 (jit-split A from C1) ============
        float C2[16][4];
        #pragma unroll
        for (int nf = 0; nf < 16; nf++)
            { C2[nf][0] = 0.f; C2[nf][1] = 0.f; C2[nf][2] = 0.f; C2[nf][3] = 0.f; }

        #pragma unroll
        for (int ks = 0; ks < 8; ks++) {
            u32 ah[4], al[4];
            bsplit2(C1[2*ks][0],   C1[2*ks][1],   ah[0], al[0]);
            bsplit2(C1[2*ks][2],   C1[2*ks][3],   ah[1], al[1]);
            bsplit2(C1[2*ks+1][0], C1[2*ks+1][1], ah[2], al[2]);
            bsplit2(C1[2*ks+1][2], C1[2*ks+1][3], ah[3], al[3]);
            #pragma unroll
            for (int p = 0; p < 8; p++) {
                u32 bh[4], bl[4];
                ldsm4(bh, bW2H + (u32)(p * 16 * PW2 + ks * 32));
                ldsm4(bl, bW2L + (u32)(p * 16 * PW2 + ks * 32));
                mma16816(C2[2*p],   ah, bh[0], bh[1]);
                mma16816(C2[2*p],   al, bh[0], bh[1]);
                mma16816(C2[2*p],   ah, bl[0], bl[1]);
                mma16816(C2[2*p+1], ah, bh[2], bh[3]);
                mma16816(C2[2*p+1], al, bh[2], bh[3]);
                mma16816(C2[2*p+1], ah, bl[2], bl[3]);
            }
        }
        // o2 = silu(C2 + br2) in place; C1 (h1) now dead
        #pragma unroll
        for (int nf = 0; nf < 16; nf++) {
            int c = nf * 8 + 2 * qk;
            float2 b2v = *(const float2*)&br2s[c];
            C2[nf][0] = silu_f(C2[nf][0] + b2v.x);
            C2[nf][1] = silu_f(C2[nf][1] + b2v.y);
            C2[nf][2] = silu_f(C2[nf][2] + b2v.x);
            C2[nf][3] = silu_f(C2[nf][3] + b2v.y);
        }

        // ============ stage E: e2pre = e1 @ we2 ============
        float CE[16][4];
        #pragma unroll
        for (int nf = 0; nf < 16; nf++)
            { CE[nf][0] = 0.f; CE[nf][1] = 0.f; CE[nf][2] = 0.f; CE[nf][3] = 0.f; }

        float i0q[4], i8q[4];
        #pragma unroll
        for (int q = 0; q < 4; q++) { i0q[q] = invw[rr * 4 + q]; i8q[q] = invw[(rr + 8) * 4 + q]; }

        #pragma unroll
        for (int ks = 0; ks < 2; ks++) {
            const int kb = 2 * qk + 16 * ks;
            u32 ah[4], al[4];
            float ev[8];
            const int kk[4] = {kb, kb + 1, kb + 8, kb + 9};
            #pragma unroll
            for (int j = 0; j < 4; j++) {
                int k = kk[j];
                float w0 = we1s[k], w1 = we1s[32 + k], w2 = we1s[64 + k], w3 = we1s[96 + k];
                float bk = be1s[k];
                float a0 = bk, a8 = bk;
                a0 = fmaf(i0q[0], w0, a0); a0 = fmaf(i0q[1], w1, a0);
                a0 = fmaf(i0q[2], w2, a0); a0 = fmaf(i0q[3], w3, a0);
                a8 = fmaf(i8q[0], w0, a8); a8 = fmaf(i8q[1], w1, a8);
                a8 = fmaf(i8q[2], w2, a8); a8 = fmaf(i8q[3], w3, a8);
                ev[j * 2]     = silu_f(a0);
                ev[j * 2 + 1] = silu_f(a8);
            }
            bsplit2(ev[0], ev[2], ah[0], al[0]);
            bsplit2(ev[1], ev[3], ah[1], al[1]);
            bsplit2(ev[4], ev[6], ah[2], al[2]);
            bsplit2(ev[5], ev[7], ah[3], al[3]);
            #pragma unroll
            for (int p = 0; p < 8; p++) {
                u32 bh[4], bl[4];
                ldsm4(bh, bWEH + (u32)(p * 16 * PW1 + ks * 32));
                ldsm4(bl, bWEL + (u32)(p * 16 * PW1 + ks * 32));
                mma16816(CE[2*p],   ah, bh[0], bh[1]);
                mma16816(CE[2*p],   al, bh[0], bh[1]);
                mma16816(CE[2*p],   ah, bl[0], bl[1]);
                mma16816(CE[2*p+1], ah, bh[2], bh[3]);
                mma16816(CE[2*p+1], al, bh[2], bh[3]);
                mma16816(CE[2*p+1], ah, bl[2], bl[3]);
            }
        }

        // ============ epilogue: out = o2 + silu(CE + be2) ============
        const int e0 = ebase + rr, e1_ = ebase + rr + 8;
        float* p0 = outw + (size_t)e0 * 128;
        float* p1 = outw + (size_t)e1_ * 128;
        #pragma unroll
        for (int nf = 0; nf < 16; nf++) {
            int c = nf * 8 + 2 * qk;
            float2 be = *(const float2*)&be2s[c];
            if (e0 < E) {
                float2 o;
                o.x = C2[nf][0] + silu_f(CE[nf][0] + be.x);
                o.y = C2[nf][1] + silu_f(CE[nf][1] + be.y);
                *(float2*)&p0[c] = o;
            }
            if (e1_ < E) {
                float2 o;
                o.x = C2[nf][2] + silu_f(CE[nf][2] + be.x);
                o.y = C2[nf][3] + silu_f(CE[nf][3] + be.y);
                *(float2*)&p1[c] = o;
            }
        }
        __syncwarp();
    }
}

// ---------------------------------------------------------------------------
// Node kernel (unchanged, ~134us)
// ---------------------------------------------------------------------------
__global__ __launch_bounds__(264, 2)
void node_kernel(const float* __restrict__ inv_f, const float* __restrict__ ev_f,
                 const float* __restrict__ w_int, const float* __restrict__ b_int,
                 float* __restrict__ out_inv, float* __restrict__ out_ev, int N)
{
    extern __shared__ float sm[];
    float* Wsh = sm;
    float* bsh = Wsh + 17424;
    float* xs  = bsh + 132;
    float* aev = xs + 4224;

    const int tx  = threadIdx.x;
    const int ty  = threadIdx.y;
    const int tid = tx + 33 * ty;
    const int NT  = 264;

    for (int i = tid; i < 17424; i += NT) Wsh[i] = w_int[i];
    if (tid < 132) bsh[tid] = b_int[tid];
    __syncthreads();

    const int nTiles = (N + 31) / 32;
    for (int tile = blockIdx.x; tile < nTiles; tile += gridDim.x) {
        const int base = tile * 32;

        for (int i = tid; i < 32 * 132; i += NT) {
            int l = i / 132, c = i % 132;
            int n = base + l;
            float v = 0.0f;
            if (n < N) {
                if (c < 128) {
                    v = 2.0f * inv_f[(size_t)n * 128 + c];
                } else {
                    const int st[5] = {0, 1, 4, 9, 16};
                    int s = c - 128;
                    float acc = 0.0f;
                    for (int k = st[s]; k < st[s + 1]; k++) {
                        float a = 2.0f * ev_f[(size_t)n * 16 + k];
                        acc = fmaf(a, a, acc);
                    }
                    v = acc;
                }
            }
            xs[l * 132 + c] = v;
        }
        for (int i = tid; i < 512; i += NT) {
            int l = i / 16, k = i % 16;
            int n = base + l;
            aev[i] = (n < N) ? 2.0f * ev_f[(size_t)n * 16 + k] : 0.0f;
        }
        __syncthreads();

        const int c0 = tx * 4;
        float acc[4][4];
        #pragma unroll
        for (int i = 0; i < 4; i++)
            #pragma unroll
            for (int k = 0; k < 4; k++) acc[i][k] = 0.0f;

        #pragma unroll 4
        for (int j = 0; j < 132; j++) {
            float4 w4 = *(const float4*)&Wsh[j * 132 + c0];
            #pragma unroll
            for (int i = 0; i < 4; i++) {
                float xv = xs[(ty * 4 + i) * 132 + j];
                acc[i][0] = fmaf(xv, w4.x, acc[i][0]);
                acc[i][1] = fmaf(xv, w4.y, acc[i][1]);
                acc[i][2] = fmaf(xv, w4.z, acc[i][2]);
                acc[i][3] = fmaf(xv, w4.w, acc[i][3]);
            }
        }

        const float4 bv = *(const float4*)&bsh[c0];
        #pragma unroll
        for (int i = 0; i < 4; i++) {
            int n = base + ty * 4 + i;
            if (n >= N) continue;
            float t0 = acc[i][0] + bv.x;
            float t1 = acc[i][1] + bv.y;
            float t2 = acc[i][2] + bv.z;
            float t3 = acc[i][3] + bv.w;
            if (tx < 32) {
                float4 o;
                o.x = xs[(ty * 4 + i) * 132 + c0 + 0] + t0;
                o.y = xs[(ty * 4 + i) * 132 + c0 + 1] + t1;
                o.z = xs[(ty * 4 + i) * 132 + c0 + 2] + t2;
                o.w = xs[(ty * 4 + i) * 132 + c0 + 3] + t3;
                *(float4*)&out_inv[(size_t)n * 128 + c0] = o;
            } else {
                float tb[4] = {t0, t1, t2, t3};
                const int SEG[16] = {0,1,1,1,2,2,2,2,2,3,3,3,3,3,3,3};
                #pragma unroll
                for (int k = 0; k < 16; k++) {
                    out_ev[(size_t)n * 16 + k] =
                        aev[(ty * 4 + i) * 16 + k] * (1.0f + tb[SEG[k]]);
                }
            }
        }
        __syncthreads();
    }
}

static const int NODE_SMEM = 22292 * 4;

extern "C" void kernel_launch(void* const* d_in, const int* in_sizes, int n_in,
                              void* d_out, int out_size)
{
    const float* inv_f     = (const float*)d_in[0];
    const float* ev_f      = (const float*)d_in[1];
    const int*   senders   = (const int*)  d_in[2];
    const int*   receivers = (const int*)  d_in[3];
    const float* lengths   = (const float*)d_in[5];

    const float* fi_rbf_w1 = (const float*)d_in[7];
    const float* fi_rbf_b1 = (const float*)d_in[8];
    const float* fi_rbf_w2 = (const float*)d_in[9];
    const float* fi_rbf_b2 = (const float*)d_in[10];
    const float* fi_ev_w1  = (const float*)d_in[11];
    const float* fi_ev_b1  = (const float*)d_in[12];
    const float* fi_ev_w2  = (const float*)d_in[13];
    const float* fi_ev_b2  = (const float*)d_in[14];
    const float* fe_rbf_w1 = (const float*)d_in[15];
    const float* fe_rbf_b1 = (const float*)d_in[16];
    const float* fe_rbf_w2 = (const float*)d_in[17];
    const float* fe_rbf_b2 = (const float*)d_in[18];
    const float* fe_ev_w1  = (const float*)d_in[19];
    const float* fe_ev_b1  = (const float*)d_in[20];
    const float* fe_ev_w2  = (const float*)d_in[21];
    const float* fe_ev_b2  = (const float*)d_in[22];
    const float* w_int     = (const float*)d_in[23];
    const float* b_int     = (const float*)d_in[24];

    const int N = in_sizes[0] / 128;
    const int E = in_sizes[2];

    float* out     = (float*)d_out;
    float* out_inv = out;
    float* out_ev  = out + (size_t)N * 128;
    float* fw_inv  = out + (size_t)N * 144;
    float* fw_ev   = fw_inv + (size_t)E * 128;

    cudaFuncSetAttribute(node_kernel,
                         cudaFuncAttributeMaxDynamicSharedMemorySize, NODE_SMEM);
    cudaFuncSetAttribute(edge_filter_mma,
                         cudaFuncAttributeMaxDynamicSharedMemorySize, EDGE_SMEM);

    edge_filter_mma<<<148, 384, EDGE_SMEM>>>(
        ev_f, senders, receivers, lengths,
        fi_rbf_w1, fi_rbf_b1, fi_rbf_w2, fi_rbf_b2,
        fi_ev_w1,  fi_ev_b1,  fi_ev_w2,  fi_ev_b2,
        fw_inv, E);

    edge_filter_mma<<<148, 384, EDGE_SMEM>>>(
        ev_f, senders, receivers, lengths,
        fe_rbf_w1, fe_rbf_b1, fe_rbf_w2, fe_rbf_b2,
        fe_ev_w1,  fe_ev_b1,  fe_ev_w2,  fe_ev_b2,
        fw_ev, E);

    node_kernel<<<304, dim3(33, 8), NODE_SMEM>>>(
        inv_f, ev_f, w_int, b_int, out_inv, out_ev, N);
}

// round 9
// speedup vs baseline: 2.7769x; 1.7634x over previous
#include <cuda_runtime.h>
#include <cuda_bf16.h>

typedef unsigned int u32;
#define FULLMASK 0xffffffffu

// silu via approx division: MUFU.RCP + FMUL instead of the ~12-instr
// IEEE div.rn.f32 sequence. Error ~2 ulp, negligible vs split-bf16 floor.
__device__ __forceinline__ float silu_f(float x){
    return __fdividef(x, 1.0f + __expf(-x));
}

__device__ __forceinline__ u32 smem_u32(const void* p){
    u32 a;
    asm("{ .reg .u64 t; cvta.to.shared.u64 t, %1; cvt.u32.u64 %0, t; }" : "=r"(a) : "l"(p));
    return a;
}
__device__ __forceinline__ void bsplit(float x, __nv_bfloat16& h, __nv_bfloat16& l){
    h = __float2bfloat16(x);
    l = __float2bfloat16(x - __bfloat162float(h));
}
__device__ __forceinline__ u32 bpack(__nv_bfloat16 a, __nv_bfloat16 b){
    return (u32)__bfloat16_as_ushort(a) | ((u32)__bfloat16_as_ushort(b) << 16);
}
__device__ __forceinline__ void bsplit2(float x0, float x1, u32& hi, u32& lo){
    __nv_bfloat16 h0, l0, h1, l1;
    bsplit(x0, h0, l0); bsplit(x1, h1, l1);
    hi = bpack(h0, h1); lo = bpack(l0, l1);
}
__device__ __forceinline__ void mma16816(float c[4], const u32 a[4], u32 b0, u32 b1){
    asm volatile(
        "mma.sync.aligned.m16n8k16.row.col.f32.bf16.bf16.f32 "
        "{%0,%1,%2,%3}, {%4,%5,%6,%7}, {%8,%9}, {%0,%1,%2,%3};"
        : "+f"(c[0]), "+f"(c[1]), "+f"(c[2]), "+f"(c[3])
        : "r"(a[0]), "r"(a[1]), "r"(a[2]), "r"(a[3]), "r"(b0), "r"(b1));
}
__device__ __forceinline__ void ldsm4(u32 r[4], u32 saddr){
    asm volatile("ldmatrix.sync.aligned.m8n8.x4.shared.b16 {%0,%1,%2,%3}, [%4];"
        : "=r"(r[0]), "=r"(r[1]), "=r"(r[2]), "=r"(r[3]) : "r"(saddr));
}

// ---------------- smem layout (bytes) ----------------
#define PW1 80
#define PW2 272
#define O_W1H 0u
#define O_W1L 10240u
#define O_WEH 20480u
#define O_WEL 30720u
#define O_W2H 40960u
#define O_W2L 75776u
#define O_BR1 110592u
#define O_BR2 111104u
#define O_BE2 111616u
#define O_BE1 112128u
#define O_WE1 112256u
#define O_WARP 112768u
#define WARP_SZ 320u
#define NWARPS 12
#define EDGE_SMEM (112768 + NWARPS * 320)   // 116608

__global__ __launch_bounds__(384, 1)
void edge_filter_mma(const float* __restrict__ evf,
                     const int*   __restrict__ senders,
                     const int*   __restrict__ receivers,
                     const float* __restrict__ lengths,
                     const float* __restrict__ wr1, const float* __restrict__ br1,
                     const float* __restrict__ wr2, const float* __restrict__ br2,
                     const float* __restrict__ we1, const float* __restrict__ be1,
                     const float* __restrict__ we2, const float* __restrict__ be2,
                     float* __restrict__ outw, int E)
{
    extern __shared__ char smc[];
    const u32 sbase = smem_u32(smc);
    const int tid  = threadIdx.x;
    const int lane = tid & 31;
    const int warp = tid >> 5;

    // ---- preload weights (transposed [n][k] + hi/lo split) ----
    for (int i = tid; i < 4096; i += 384) {          // wr1 [32k][128n]
        int n = i & 127, k = i >> 7;
        __nv_bfloat16 h, l; bsplit(wr1[k * 128 + n], h, l);
        *(__nv_bfloat16*)(smc + O_W1H + n * PW1 + k * 2) = h;
        *(__nv_bfloat16*)(smc + O_W1L + n * PW1 + k * 2) = l;
    }
    for (int i = tid; i < 4096; i += 384) {          // we2 [32k][128n]
        int n = i & 127, k = i >> 7;
        __nv_bfloat16 h, l; bsplit(we2[k * 128 + n], h, l);
        *(__nv_bfloat16*)(smc + O_WEH + n * PW1 + k * 2) = h;
        *(__nv_bfloat16*)(smc + O_WEL + n * PW1 + k * 2) = l;
    }
    for (int i = tid; i < 16384; i += 384) {         // wr2 [128k][128n]
        int n = i & 127, k = i >> 7;
        __nv_bfloat16 h, l; bsplit(wr2[k * 128 + n], h, l);
        *(__nv_bfloat16*)(smc + O_W2H + n * PW2 + k * 2) = h;
        *(__nv_bfloat16*)(smc + O_W2L + n * PW2 + k * 2) = l;
    }
    float* br1s = (float*)(smc + O_BR1);
    float* br2s = (float*)(smc + O_BR2);
    float* be2s = (float*)(smc + O_BE2);
    float* be1s = (float*)(smc + O_BE1);
    float* we1s = (float*)(smc + O_WE1);
    if (tid < 128) { br1s[tid] = br1[tid]; br2s[tid] = br2[tid];
                     be2s[tid] = be2[tid]; we1s[tid] = we1[tid]; }
    if (tid < 32)  be1s[tid] = be1[tid];
    __syncthreads();

    char* wbase = smc + O_WARP + warp * WARP_SZ;
    float* invw = (float*)(wbase);          // [16][4]
    float* lenw = (float*)(wbase + 256);    // [16]

    const int qk = lane & 3;
    const int rr = lane >> 2;
    const float STEP = 5.0f / 31.0f;
    const float GAMMA = 0.5f * (31.0f / 5.0f) * (31.0f / 5.0f);

    // ldmatrix lane-constant address parts
    const u32 lrow  = (u32)((lane & 7) + ((lane & 16) >> 1));
    const u32 lcolB = (u32)((lane & 8) << 1);
    const u32 bW1H = sbase + O_W1H + lrow * PW1 + lcolB;
    const u32 bW1L = sbase + O_W1L + lrow * PW1 + lcolB;
    const u32 bWEH = sbase + O_WEH + lrow * PW1 + lcolB;
    const u32 bWEL = sbase + O_WEL + lrow * PW1 + lcolB;
    const u32 bW2H = sbase + O_W2H + lrow * PW2 + lcolB;
    const u32 bW2L = sbase + O_W2L + lrow * PW2 + lcolB;

    const int nGroups = (E + 15) >> 4;
    const int gstride = gridDim.x * NWARPS;

    for (int g = blockIdx.x * NWARPS + warp; g < nGroups; g += gstride) {
        const int ebase = g * 16;

        // ---- edge meta ----
        int sI = 0, rI = 0;
        if (lane < 16) {
            int ge = ebase + lane; if (ge >= E) ge = E - 1;
            sI = senders[ge]; rI = receivers[ge];
            lenw[lane] = lengths[ge];
        }
        {   // invariants: 2 lanes per edge
            int m = lane >> 1, half = lane & 1;
            int sm_ = __shfl_sync(FULLMASK, sI, m);
            int rm_ = __shfl_sync(FULLMASK, rI, m);
            const float4* ps = (const float4*)(evf + (size_t)sm_ * 16 + half * 8);
            const float4* pr = (const float4*)(evf + (size_t)rm_ * 16 + half * 8);
            float4 sa = ps[0], sb = ps[1], ra = pr[0], rb = pr[1];
            float d[8];
            d[0] = sa.x - ra.x; d[1] = sa.y - ra.y; d[2] = sa.z - ra.z; d[3] = sa.w - ra.w;
            d[4] = sb.x - rb.x; d[5] = sb.y - rb.y; d[6] = sb.z - rb.z; d[7] = sb.w - rb.w;
            #pragma unroll
            for (int i = 0; i < 8; i++) d[i] *= d[i];
            float q0, q1, q2p, q3p;
            if (half == 0) {
                q0 = d[0]; q1 = d[1] + d[2] + d[3];
                q2p = d[4] + d[5] + d[6] + d[7]; q3p = 0.0f;
            } else {
                q0 = 0.0f; q1 = 0.0f; q2p = d[0];
                q3p = d[1] + d[2] + d[3] + d[4] + d[5] + d[6] + d[7];
            }
            float q0f = q0 + __shfl_xor_sync(FULLMASK, q0, 1);
            float q1f = q1 + __shfl_xor_sync(FULLMASK, q1, 1);
            float q2f = q2p + __shfl_xor_sync(FULLMASK, q2p, 1);
            float q3f = q3p + __shfl_xor_sync(FULLMASK, q3p, 1);
            if (half == 0) {
                invw[m * 4 + 0] = q0f; invw[m * 4 + 1] = q1f;
                invw[m * 4 + 2] = q2f; invw[m * 4 + 3] = q3f;
            }
        }
        __syncwarp();

        // ============ stage 1: h1pre = rbf @ wr1 ============
        float C1[16][4];
        #pragma unroll
        for (int nf = 0; nf < 16; nf++)
            { C1[nf][0] = 0.f; C1[nf][1] = 0.f; C1[nf][2] = 0.f; C1[nf][3] = 0.f; }

        const float lm0 = lenw[rr], lm8 = lenw[rr + 8];
        #pragma unroll
        for (int ks = 0; ks < 2; ks++) {
            const int kb = 2 * qk + 16 * ks;
            float c0 = (float)kb * STEP, c1 = (float)(kb + 1) * STEP;
            float c8 = (float)(kb + 8) * STEP, c9 = (float)(kb + 9) * STEP;
            float t;
            u32 ah[4], al[4];
            t = lm0 - c0; float v0 = __expf(-GAMMA * t * t);
            t = lm0 - c1; float v1 = __expf(-GAMMA * t * t);
            t = lm8 - c0; float v2 = __expf(-GAMMA * t * t);
            t = lm8 - c1; float v3 = __expf(-GAMMA * t * t);
            t = lm0 - c8; float v4 = __expf(-GAMMA * t * t);
            t = lm0 - c9; float v5 = __expf(-GAMMA * t * t);
            t = lm8 - c8; float v6 = __expf(-GAMMA * t * t);
            t = lm8 - c9; float v7 = __expf(-GAMMA * t * t);
            bsplit2(v0, v1, ah[0], al[0]); bsplit2(v2, v3, ah[1], al[1]);
            bsplit2(v4, v5, ah[2], al[2]); bsplit2(v6, v7, ah[3], al[3]);
            #pragma unroll
            for (int p = 0; p < 8; p++) {
                u32 bh[4], bl[4];
                ldsm4(bh, bW1H + (u32)(p * 16 * PW1 + ks * 32));
                ldsm4(bl, bW1L + (u32)(p * 16 * PW1 + ks * 32));
                mma16816(C1[2*p],   ah, bh[0], bh[1]);
                mma16816(C1[2*p],   al, bh[0], bh[1]);
                mma16816(C1[2*p],   ah, bl[0], bl[1]);
                mma16816(C1[2*p+1], ah, bh[2], bh[3]);
                mma16816(C1[2*p+1], al, bh[2], bh[3]);
                mma16816(C1[2*p+1], ah, bl[2], bl[3]);
            }
        }
        // h1 = silu(C1 + br1), kept in registers (C layout == A layout)
        #pragma unroll
        for (int nf = 0; nf < 16; nf++) {
            int c = nf * 8 + 2 * qk;
            float2 b1v = *(const float2*)&br1s[c];
            C1[nf][0] = silu_f(C1[nf][0] + b1v.x);
            C1[nf][1] = silu_f(C1[nf][1] + b1v.y);
            C1[nf][2] = silu_f(C1[nf][2] + b1v.x);
            C1[nf][3] = silu_f(C1[nf][3] + b1v.y);
        }

        // ============ stage 2: h2pre = h1 @ wr2 (jit-split A from C1) ============
        float C2[16][4];
        #pragma unroll
        for (int nf = 0; nf < 16; nf++)
            { C2[nf][0] = 0.f; C2[nf][1] = 0.f; C2[nf][2] = 0.f; C2[nf][3] = 0.f; }

        #pragma unroll
        for (int ks = 0; ks < 8; ks++) {
            u32 ah[4], al[4];
            bsplit2(C1[2*ks][0],   C1[2*ks][1],   ah[0], al[0]);
            bsplit2(C1[2*ks][2],   C1[2*ks][3],   ah[1], al[1]);
            bsplit2(C1[2*ks+1][0], C1[2*ks+1][1], ah[2], al[2]);
            bsplit2(C1[2*ks+1][2], C1[2*ks+1][3], ah[3], al[3]);
            #pragma unroll
            for (int p = 0; p < 8; p++) {
                u32 bh[4], bl[4];
                ldsm4(bh, bW2H + (u32)(p * 16 * PW2 + ks * 32));
                ldsm4(bl, bW2L + (u32)(p * 16 * PW2 + ks * 32));
                mma16816(C2[2*p],   ah, bh[0], bh[1]);
                mma16816(C2[2*p],   al, bh[0], bh[1]);
                mma16816(C2[2*p],   ah, bl[0], bl[1]);
                mma16816(C2[2*p+1], ah, bh[2], bh[3]);
                mma16816(C2[2*p+1], al, bh[2], bh[3]);
                mma16816(C2[2*p+1], ah, bl[2], bl[3]);
            }
        }
        // o2 = silu(C2 + br2) in place; C1 (h1) now dead
        #pragma unroll
        for (int nf = 0; nf < 16; nf++) {
            int c = nf * 8 + 2 * qk;
            float2 b2v = *(const float2*)&br2s[c];
            C2[nf][0] = silu_f(C2[nf][0] + b2v.x);
            C2[nf][1] = silu_f(C2[nf][1] + b2v.y);
            C2[nf][2] = silu_f(C2[nf][2] + b2v.x);
            C2[nf][3] = silu_f(C2[nf][3] + b2v.y);
        }

        // ============ stage E: e2pre = e1 @ we2 ============
        float CE[16][4];
        #pragma unroll
        for (int nf = 0; nf < 16; nf++)
            { CE[nf][0] = 0.f; CE[nf][1] = 0.f; CE[nf][2] = 0.f; CE[nf][3] = 0.f; }

        float i0q[4], i8q[4];
        #pragma unroll
        for (int q = 0; q < 4; q++) { i0q[q] = invw[rr * 4 + q]; i8q[q] = invw[(rr + 8) * 4 + q]; }

        #pragma unroll
        for (int ks = 0; ks < 2; ks++) {
            const int kb = 2 * qk + 16 * ks;
            u32 ah[4], al[4];
            float ev[8];
            const int kk[4] = {kb, kb + 1, kb + 8, kb + 9};
            #pragma unroll
            for (int j = 0; j < 4; j++) {
                int k = kk[j];
                float w0 = we1s[k], w1 = we1s[32 + k], w2 = we1s[64 + k], w3 = we1s[96 + k];
                float bk = be1s[k];
                float a0 = bk, a8 = bk;
                a0 = fmaf(i0q[0], w0, a0); a0 = fmaf(i0q[1], w1, a0);
                a0 = fmaf(i0q[2], w2, a0); a0 = fmaf(i0q[3], w3, a0);
                a8 = fmaf(i8q[0], w0, a8); a8 = fmaf(i8q[1], w1, a8);
                a8 = fmaf(i8q[2], w2, a8); a8 = fmaf(i8q[3], w3, a8);
                ev[j * 2]     = silu_f(a0);
                ev[j * 2 + 1] = silu_f(a8);
            }
            bsplit2(ev[0], ev[2], ah[0], al[0]);
            bsplit2(ev[1], ev[3], ah[1], al[1]);
            bsplit2(ev[4], ev[6], ah[2], al[2]);
            bsplit2(ev[5], ev[7], ah[3], al[3]);
            #pragma unroll
            for (int p = 0; p < 8; p++) {
                u32 bh[4], bl[4];
                ldsm4(bh, bWEH + (u32)(p * 16 * PW1 + ks * 32));
                ldsm4(bl, bWEL + (u32)(p * 16 * PW1 + ks * 32));
                mma16816(CE[2*p],   ah, bh[0], bh[1]);
                mma16816(CE[2*p],   al, bh[0], bh[1]);
                mma16816(CE[2*p],   ah, bl[0], bl[1]);
                mma16816(CE[2*p+1], ah, bh[2], bh[3]);
                mma16816(CE[2*p+1], al, bh[2], bh[3]);
                mma16816(CE[2*p+1], ah, bl[2], bl[3]);
            }
        }

        // ============ epilogue: out = o2 + silu(CE + be2) ============
        const int e0 = ebase + rr, e1_ = ebase + rr + 8;
        float* p0 = outw + (size_t)e0 * 128;
        float* p1 = outw + (size_t)e1_ * 128;
        #pragma unroll
        for (int nf = 0; nf < 16; nf++) {
            int c = nf * 8 + 2 * qk;
            float2 be = *(const float2*)&be2s[c];
            if (e0 < E) {
                float2 o;
                o.x = C2[nf][0] + silu_f(CE[nf][0] + be.x);
                o.y = C2[nf][1] + silu_f(CE[nf][1] + be.y);
                *(float2*)&p0[c] = o;
            }
            if (e1_ < E) {
                float2 o;
                o.x = C2[nf][2] + silu_f(CE[nf][2] + be.x);
                o.y = C2[nf][3] + silu_f(CE[nf][3] + be.y);
                *(float2*)&p1[c] = o;
            }
        }
        __syncwarp();
    }
}

// ---------------------------------------------------------------------------
// Node kernel (unchanged, ~134us)
// ---------------------------------------------------------------------------
__global__ __launch_bounds__(264, 2)
void node_kernel(const float* __restrict__ inv_f, const float* __restrict__ ev_f,
                 const float* __restrict__ w_int, const float* __restrict__ b_int,
                 float* __restrict__ out_inv, float* __restrict__ out_ev, int N)
{
    extern __shared__ float sm[];
    float* Wsh = sm;
    float* bsh = Wsh + 17424;
    float* xs  = bsh + 132;
    float* aev = xs + 4224;

    const int tx  = threadIdx.x;
    const int ty  = threadIdx.y;
    const int tid = tx + 33 * ty;
    const int NT  = 264;

    for (int i = tid; i < 17424; i += NT) Wsh[i] = w_int[i];
    if (tid < 132) bsh[tid] = b_int[tid];
    __syncthreads();

    const int nTiles = (N + 31) / 32;
    for (int tile = blockIdx.x; tile < nTiles; tile += gridDim.x) {
        const int base = tile * 32;

        for (int i = tid; i < 32 * 132; i += NT) {
            int l = i / 132, c = i % 132;
            int n = base + l;
            float v = 0.0f;
            if (n < N) {
                if (c < 128) {
                    v = 2.0f * inv_f[(size_t)n * 128 + c];
                } else {
                    const int st[5] = {0, 1, 4, 9, 16};
                    int s = c - 128;
                    float acc = 0.0f;
                    for (int k = st[s]; k < st[s + 1]; k++) {
                        float a = 2.0f * ev_f[(size_t)n * 16 + k];
                        acc = fmaf(a, a, acc);
                    }
                    v = acc;
                }
            }
            xs[l * 132 + c] = v;
        }
        for (int i = tid; i < 512; i += NT) {
            int l = i / 16, k = i % 16;
            int n = base + l;
            aev[i] = (n < N) ? 2.0f * ev_f[(size_t)n * 16 + k] : 0.0f;
        }
        __syncthreads();

        const int c0 = tx * 4;
        float acc[4][4];
        #pragma unroll
        for (int i = 0; i < 4; i++)
            #pragma unroll
            for (int k = 0; k < 4; k++) acc[i][k] = 0.0f;

        #pragma unroll 4
        for (int j = 0; j < 132; j++) {
            float4 w4 = *(const float4*)&Wsh[j * 132 + c0];
            #pragma unroll
            for (int i = 0; i < 4; i++) {
                float xv = xs[(ty * 4 + i) * 132 + j];
                acc[i][0] = fmaf(xv, w4.x, acc[i][0]);
                acc[i][1] = fmaf(xv, w4.y, acc[i][1]);
                acc[i][2] = fmaf(xv, w4.z, acc[i][2]);
                acc[i][3] = fmaf(xv, w4.w, acc[i][3]);
            }
        }

        const float4 bv = *(const float4*)&bsh[c0];
        #pragma unroll
        for (int i = 0; i < 4; i++) {
            int n = base + ty * 4 + i;
            if (n >= N) continue;
            float t0 = acc[i][0] + bv.x;
            float t1 = acc[i][1] + bv.y;
            float t2 = acc[i][2] + bv.z;
            float t3 = acc[i][3] + bv.w;
            if (tx < 32) {
                float4 o;
                o.x = xs[(ty * 4 + i) * 132 + c0 + 0] + t0;
                o.y = xs[(ty * 4 + i) * 132 + c0 + 1] + t1;
                o.z = xs[(ty * 4 + i) * 132 + c0 + 2] + t2;
                o.w = xs[(ty * 4 + i) * 132 + c0 + 3] + t3;
                *(float4*)&out_inv[(size_t)n * 128 + c0] = o;
            } else {
                float tb[4] = {t0, t1, t2, t3};
                const int SEG[16] = {0,1,1,1,2,2,2,2,2,3,3,3,3,3,3,3};
                #pragma unroll
                for (int k = 0; k < 16; k++) {
                    out_ev[(size_t)n * 16 + k] =
                        aev[(ty * 4 + i) * 16 + k] * (1.0f + tb[SEG[k]]);
                }
            }
        }
        __syncthreads();
    }
}

static const int NODE_SMEM = 22292 * 4;

extern "C" void kernel_launch(void* const* d_in, const int* in_sizes, int n_in,
                              void* d_out, int out_size)
{
    const float* inv_f     = (const float*)d_in[0];
    const float* ev_f      = (const float*)d_in[1];
    const int*   senders   = (const int*)  d_in[2];
    const int*   receivers = (const int*)  d_in[3];
    const float* lengths   = (const float*)d_in[5];

    const float* fi_rbf_w1 = (const float*)d_in[7];
    const float* fi_rbf_b1 = (const float*)d_in[8];
    const float* fi_rbf_w2 = (const float*)d_in[9];
    const float* fi_rbf_b2 = (const float*)d_in[10];
    const float* fi_ev_w1  = (const float*)d_in[11];
    const float* fi_ev_b1  = (const float*)d_in[12];
    const float* fi_ev_w2  = (const float*)d_in[13];
    const float* fi_ev_b2  = (const float*)d_in[14];
    const float* fe_rbf_w1 = (const float*)d_in[15];
    const float* fe_rbf_b1 = (const float*)d_in[16];
    const float* fe_rbf_w2 = (const float*)d_in[17];
    const float* fe_rbf_b2 = (const float*)d_in[18];
    const float* fe_ev_w1  = (const float*)d_in[19];
    const float* fe_ev_b1  = (const float*)d_in[20];
    const float* fe_ev_w2  = (const float*)d_in[21];
    const float* fe_ev_b2  = (const float*)d_in[22];
    const float* w_int     = (const float*)d_in[23];
    const float* b_int     = (const float*)d_in[24];

    const int N = in_sizes[0] / 128;
    const int E = in_sizes[2];

    float* out     = (float*)d_out;
    float* out_inv = out;
    float* out_ev  = out + (size_t)N * 128;
    float* fw_inv  = out + (size_t)N * 144;
    float* fw_ev   = fw_inv + (size_t)E * 128;

    cudaFuncSetAttribute(node_kernel,
                         cudaFuncAttributeMaxDynamicSharedMemorySize, NODE_SMEM);
    cudaFuncSetAttribute(edge_filter_mma,
                         cudaFuncAttributeMaxDynamicSharedMemorySize, EDGE_SMEM);

    edge_filter_mma<<<148, 384, EDGE_SMEM>>>(
        ev_f, senders, receivers, lengths,
        fi_rbf_w1, fi_rbf_b1, fi_rbf_w2, fi_rbf_b2,
        fi_ev_w1,  fi_ev_b1,  fi_ev_w2,  fi_ev_b2,
        fw_inv, E);

    edge_filter_mma<<<148, 384, EDGE_SMEM>>>(
        ev_f, senders, receivers, lengths,
        fe_rbf_w1, fe_rbf_b1, fe_rbf_w2, fe_rbf_b2,
        fe_ev_w1,  fe_ev_b1,  fe_ev_w2,  fe_ev_b2,
        fw_ev, E);

    node_kernel<<<304, dim3(33, 8), NODE_SMEM>>>(
        inv_f, ev_f, w_int, b_int, out_inv, out_ev, N);
}

// round 10
// speedup vs baseline: 2.9167x; 1.0503x over previous
#include <cuda_runtime.h>
#include <cuda_bf16.h>

typedef unsigned int u32;
#define FULLMASK 0xffffffffu

__device__ __forceinline__ float silu_f(float x){
    return __fdividef(x, 1.0f + __expf(-x));
}

__device__ __forceinline__ u32 smem_u32(const void* p){
    u32 a;
    asm("{ .reg .u64 t; cvta.to.shared.u64 t, %1; cvt.u32.u64 %0, t; }" : "=r"(a) : "l"(p));
    return a;
}
__device__ __forceinline__ void bsplit(float x, __nv_bfloat16& h, __nv_bfloat16& l){
    h = __float2bfloat16(x);
    l = __float2bfloat16(x - __bfloat162float(h));
}
__device__ __forceinline__ u32 bpack(__nv_bfloat16 a, __nv_bfloat16 b){
    return (u32)__bfloat16_as_ushort(a) | ((u32)__bfloat16_as_ushort(b) << 16);
}
__device__ __forceinline__ void bsplit2(float x0, float x1, u32& hi, u32& lo){
    __nv_bfloat16 h0, l0, h1, l1;
    bsplit(x0, h0, l0); bsplit(x1, h1, l1);
    hi = bpack(h0, h1); lo = bpack(l0, l1);
}
__device__ __forceinline__ void mma16816(float c[4], const u32 a[4], u32 b0, u32 b1){
    asm volatile(
        "mma.sync.aligned.m16n8k16.row.col.f32.bf16.bf16.f32 "
        "{%0,%1,%2,%3}, {%4,%5,%6,%7}, {%8,%9}, {%0,%1,%2,%3};"
        : "+f"(c[0]), "+f"(c[1]), "+f"(c[2]), "+f"(c[3])
        : "r"(a[0]), "r"(a[1]), "r"(a[2]), "r"(a[3]), "r"(b0), "r"(b1));
}
__device__ __forceinline__ void ldsm4(u32 r[4], u32 saddr){
    asm volatile("ldmatrix.sync.aligned.m8n8.x4.shared.b16 {%0,%1,%2,%3}, [%4];"
        : "=r"(r[0]), "=r"(r[1]), "=r"(r[2]), "=r"(r[3]) : "r"(saddr));
}

// ---------------- smem layout (bytes) ----------------
#define PW1 80
#define PW2 272
#define O_W1H 0u
#define O_W1L 10240u
#define O_WEH 20480u
#define O_WEL 30720u
#define O_W2H 40960u
#define O_W2L 75776u
#define O_BR1 110592u
#define O_BR2 111104u
#define O_BE2 111616u
#define O_BE1 112128u
#define O_WE1 112256u
#define NWARPS 12
#define EDGE_SMEM 112768

__global__ __launch_bounds__(384, 1)
void edge_filter_mma(const float* __restrict__ evf,
                     const int*   __restrict__ senders,
                     const int*   __restrict__ receivers,
                     const float* __restrict__ lengths,
                     const float* __restrict__ wr1, const float* __restrict__ br1,
                     const float* __restrict__ wr2, const float* __restrict__ br2,
                     const float* __restrict__ we1, const float* __restrict__ be1,
                     const float* __restrict__ we2, const float* __restrict__ be2,
                     float* __restrict__ outw, int E)
{
    extern __shared__ char smc[];
    const u32 sbase = smem_u32(smc);
    const int tid  = threadIdx.x;
    const int lane = tid & 31;
    const int warp = tid >> 5;

    // ---- preload weights (transposed [n][k] + hi/lo split) ----
    for (int i = tid; i < 4096; i += 384) {          // wr1 [32k][128n]
        int n = i & 127, k = i >> 7;
        __nv_bfloat16 h, l; bsplit(wr1[k * 128 + n], h, l);
        *(__nv_bfloat16*)(smc + O_W1H + n * PW1 + k * 2) = h;
        *(__nv_bfloat16*)(smc + O_W1L + n * PW1 + k * 2) = l;
    }
    for (int i = tid; i < 4096; i += 384) {          // we2 [32k][128n]
        int n = i & 127, k = i >> 7;
        __nv_bfloat16 h, l; bsplit(we2[k * 128 + n], h, l);
        *(__nv_bfloat16*)(smc + O_WEH + n * PW1 + k * 2) = h;
        *(__nv_bfloat16*)(smc + O_WEL + n * PW1 + k * 2) = l;
    }
    for (int i = tid; i < 16384; i += 384) {         // wr2 [128k][128n]
        int n = i & 127, k = i >> 7;
        __nv_bfloat16 h, l; bsplit(wr2[k * 128 + n], h, l);
        *(__nv_bfloat16*)(smc + O_W2H + n * PW2 + k * 2) = h;
        *(__nv_bfloat16*)(smc + O_W2L + n * PW2 + k * 2) = l;
    }
    float* br1s = (float*)(smc + O_BR1);
    float* br2s = (float*)(smc + O_BR2);
    float* be2s = (float*)(smc + O_BE2);
    float* be1s = (float*)(smc + O_BE1);
    float* we1s = (float*)(smc + O_WE1);
    if (tid < 128) { br1s[tid] = br1[tid]; br2s[tid] = br2[tid];
                     be2s[tid] = be2[tid]; we1s[tid] = we1[tid]; }
    if (tid < 32)  be1s[tid] = be1[tid];
    __syncthreads();

    const int qk = lane & 3;
    const int rr = lane >> 2;
    const float STEP = 5.0f / 31.0f;
    const float GAMMA = 0.5f * (31.0f / 5.0f) * (31.0f / 5.0f);

    // ldmatrix lane-constant address parts
    const u32 lrow  = (u32)((lane & 7) + ((lane & 16) >> 1));
    const u32 lcolB = (u32)((lane & 8) << 1);
    const u32 bW1H = sbase + O_W1H + lrow * PW1 + lcolB;
    const u32 bW1L = sbase + O_W1L + lrow * PW1 + lcolB;
    const u32 bWEH = sbase + O_WEH + lrow * PW1 + lcolB;
    const u32 bWEL = sbase + O_WEL + lrow * PW1 + lcolB;
    const u32 bW2H = sbase + O_W2H + lrow * PW2 + lcolB;
    const u32 bW2L = sbase + O_W2L + lrow * PW2 + lcolB;

    const int nGroups = (E + 15) >> 4;
    const int gstride = gridDim.x * NWARPS;

    for (int g = blockIdx.x * NWARPS + warp; g < nGroups; g += gstride) {
        const int ebase = g * 16;

        // ---- gather + invariants (barrier-free: shuffles only) ----
        // pair (2m, 2m+1) computes edge m's 4 seg-invariants
        float q0f, q1f, q2f, q3f;
        {
            int m = lane >> 1, half = lane & 1;
            int gm = ebase + m; if (gm >= E) gm = E - 1;
            int sm_ = senders[gm], rm_ = receivers[gm];
            const float4* ps = (const float4*)(evf + (size_t)sm_ * 16 + half * 8);
            const float4* pr = (const float4*)(evf + (size_t)rm_ * 16 + half * 8);
            float4 sa = ps[0], sb = ps[1], ra = pr[0], rb = pr[1];
            float d[8];
            d[0] = sa.x - ra.x; d[1] = sa.y - ra.y; d[2] = sa.z - ra.z; d[3] = sa.w - ra.w;
            d[4] = sb.x - rb.x; d[5] = sb.y - rb.y; d[6] = sb.z - rb.z; d[7] = sb.w - rb.w;
            #pragma unroll
            for (int i = 0; i < 8; i++) d[i] *= d[i];
            float q0, q1, q2p, q3p;
            if (half == 0) {
                q0 = d[0]; q1 = d[1] + d[2] + d[3];
                q2p = d[4] + d[5] + d[6] + d[7]; q3p = 0.0f;
            } else {
                q0 = 0.0f; q1 = 0.0f; q2p = d[0];
                q3p = d[1] + d[2] + d[3] + d[4] + d[5] + d[6] + d[7];
            }
            q0f = q0 + __shfl_xor_sync(FULLMASK, q0, 1);
            q1f = q1 + __shfl_xor_sync(FULLMASK, q1, 1);
            q2f = q2p + __shfl_xor_sync(FULLMASK, q2p, 1);
            q3f = q3p + __shfl_xor_sync(FULLMASK, q3p, 1);
        }
        // lane needs invariants of edges rr and rr+8 (held by lanes 2rr / 2rr+16)
        const int src0 = rr << 1, src8 = (rr << 1) + 16;
        float i0q[4], i8q[4];
        i0q[0] = __shfl_sync(FULLMASK, q0f, src0);
        i0q[1] = __shfl_sync(FULLMASK, q1f, src0);
        i0q[2] = __shfl_sync(FULLMASK, q2f, src0);
        i0q[3] = __shfl_sync(FULLMASK, q3f, src0);
        i8q[0] = __shfl_sync(FULLMASK, q0f, src8);
        i8q[1] = __shfl_sync(FULLMASK, q1f, src8);
        i8q[2] = __shfl_sync(FULLMASK, q2f, src8);
        i8q[3] = __shfl_sync(FULLMASK, q3f, src8);

        // lengths: direct loads (L2-hot, broadcast across 4 lanes)
        int ge0 = ebase + rr;      if (ge0 >= E) ge0 = E - 1;
        int ge8 = ebase + rr + 8;  if (ge8 >= E) ge8 = E - 1;
        const float lm0 = lengths[ge0], lm8 = lengths[ge8];

        // ---- e1 A-fragments (hoisted before stage1) ----
        u32 eAh[2][4], eAl[2][4];
        #pragma unroll
        for (int ks = 0; ks < 2; ks++) {
            const int kb = 2 * qk + 16 * ks;
            float ev[8];
            const int kk[4] = {kb, kb + 1, kb + 8, kb + 9};
            #pragma unroll
            for (int j = 0; j < 4; j++) {
                int k = kk[j];
                float w0 = we1s[k], w1 = we1s[32 + k], w2 = we1s[64 + k], w3 = we1s[96 + k];
                float bk = be1s[k];
                float a0 = bk, a8 = bk;
                a0 = fmaf(i0q[0], w0, a0); a0 = fmaf(i0q[1], w1, a0);
                a0 = fmaf(i0q[2], w2, a0); a0 = fmaf(i0q[3], w3, a0);
                a8 = fmaf(i8q[0], w0, a8); a8 = fmaf(i8q[1], w1, a8);
                a8 = fmaf(i8q[2], w2, a8); a8 = fmaf(i8q[3], w3, a8);
                ev[j * 2]     = silu_f(a0);
                ev[j * 2 + 1] = silu_f(a8);
            }
            bsplit2(ev[0], ev[2], eAh[ks][0], eAl[ks][0]);
            bsplit2(ev[1], ev[3], eAh[ks][1], eAl[ks][1]);
            bsplit2(ev[4], ev[6], eAh[ks][2], eAl[ks][2]);
            bsplit2(ev[5], ev[7], eAh[ks][3], eAl[ks][3]);
        }

        // ============ stage 1: h1pre = rbf @ wr1 ============
        float C1[16][4];
        #pragma unroll
        for (int nf = 0; nf < 16; nf++)
            { C1[nf][0] = 0.f; C1[nf][1] = 0.f; C1[nf][2] = 0.f; C1[nf][3] = 0.f; }

        #pragma unroll
        for (int ks = 0; ks < 2; ks++) {
            const int kb = 2 * qk + 16 * ks;
            float c0 = (float)kb * STEP, c1 = (float)(kb + 1) * STEP;
            float c8 = (float)(kb + 8) * STEP, c9 = (float)(kb + 9) * STEP;
            float t;
            u32 ah[4], al[4];
            t = lm0 - c0; float v0 = __expf(-GAMMA * t * t);
            t = lm0 - c1; float v1 = __expf(-GAMMA * t * t);
            t = lm8 - c0; float v2 = __expf(-GAMMA * t * t);
            t = lm8 - c1; float v3 = __expf(-GAMMA * t * t);
            t = lm0 - c8; float v4 = __expf(-GAMMA * t * t);
            t = lm0 - c9; float v5 = __expf(-GAMMA * t * t);
            t = lm8 - c8; float v6 = __expf(-GAMMA * t * t);
            t = lm8 - c9; float v7 = __expf(-GAMMA * t * t);
            bsplit2(v0, v1, ah[0], al[0]); bsplit2(v2, v3, ah[1], al[1]);
            bsplit2(v4, v5, ah[2], al[2]); bsplit2(v6, v7, ah[3], al[3]);
            #pragma unroll
            for (int p = 0; p < 8; p++) {
                u32 bh[4], bl[4];
                ldsm4(bh, bW1H + (u32)(p * 16 * PW1 + ks * 32));
                ldsm4(bl, bW1L + (u32)(p * 16 * PW1 + ks * 32));
                mma16816(C1[2*p],   ah, bh[0], bh[1]);
                mma16816(C1[2*p],   al, bh[0], bh[1]);
                mma16816(C1[2*p],   ah, bl[0], bl[1]);
                mma16816(C1[2*p+1], ah, bh[2], bh[3]);
                mma16816(C1[2*p+1], al, bh[2], bh[3]);
                mma16816(C1[2*p+1], ah, bl[2], bl[3]);
            }
        }
        // h1 = silu(C1 + br1), kept in registers (C layout == A layout)
        #pragma unroll
        for (int nf = 0; nf < 16; nf++) {
            int c = nf * 8 + 2 * qk;
            float2 b1v = *(const float2*)&br1s[c];
            C1[nf][0] = silu_f(C1[nf][0] + b1v.x);
            C1[nf][1] = silu_f(C1[nf][1] + b1v.y);
            C1[nf][2] = silu_f(C1[nf][2] + b1v.x);
            C1[nf][3] = silu_f(C1[nf][3] + b1v.y);
        }

        // ============ stage 2: h2pre = h1 @ wr2 (jit-split A from C1) ============
        float C2[16][4];
        #pragma unroll
        for (int nf = 0; nf < 16; nf++)
            { C2[nf][0] = 0.f; C2[nf][1] = 0.f; C2[nf][2] = 0.f; C2[nf][3] = 0.f; }

        #pragma unroll
        for (int ks = 0; ks < 8; ks++) {
            u32 ah[4], al[4];
            bsplit2(C1[2*ks][0],   C1[2*ks][1],   ah[0], al[0]);
            bsplit2(C1[2*ks][2],   C1[2*ks][3],   ah[1], al[1]);
            bsplit2(C1[2*ks+1][0], C1[2*ks+1][1], ah[2], al[2]);
            bsplit2(C1[2*ks+1][2], C1[2*ks+1][3], ah[3], al[3]);
            #pragma unroll
            for (int p = 0; p < 8; p++) {
                u32 bh[4], bl[4];
                ldsm4(bh, bW2H + (u32)(p * 16 * PW2 + ks * 32));
                ldsm4(bl, bW2L + (u32)(p * 16 * PW2 + ks * 32));
                mma16816(C2[2*p],   ah, bh[0], bh[1]);
                mma16816(C2[2*p],   al, bh[0], bh[1]);
                mma16816(C2[2*p],   ah, bl[0], bl[1]);
                mma16816(C2[2*p+1], ah, bh[2], bh[3]);
                mma16816(C2[2*p+1], al, bh[2], bh[3]);
                mma16816(C2[2*p+1], ah, bl[2], bl[3]);
            }
        }

        // ============ stage E: e2pre = e1 @ we2 (contiguous with stage2) ============
        float CE[16][4];
        #pragma unroll
        for (int nf = 0; nf < 16; nf++)
            { CE[nf][0] = 0.f; CE[nf][1] = 0.f; CE[nf][2] = 0.f; CE[nf][3] = 0.f; }

        #pragma unroll
        for (int ks = 0; ks < 2; ks++) {
            #pragma unroll
            for (int p = 0; p < 8; p++) {
                u32 bh[4], bl[4];
                ldsm4(bh, bWEH + (u32)(p * 16 * PW1 + ks * 32));
                ldsm4(bl, bWEL + (u32)(p * 16 * PW1 + ks * 32));
                mma16816(CE[2*p],   eAh[ks], bh[0], bh[1]);
                mma16816(CE[2*p],   eAl[ks], bh[0], bh[1]);
                mma16816(CE[2*p],   eAh[ks], bl[0], bl[1]);
                mma16816(CE[2*p+1], eAh[ks], bh[2], bh[3]);
                mma16816(CE[2*p+1], eAl[ks], bh[2], bh[3]);
                mma16816(CE[2*p+1], eAh[ks], bl[2], bl[3]);
            }
        }

        // ============ epilogue: out = silu(C2+br2) + silu(CE+be2) ============
        const int e0 = ebase + rr, e1_ = ebase + rr + 8;
        float* p0 = outw + (size_t)e0 * 128;
        float* p1 = outw + (size_t)e1_ * 128;
        #pragma unroll
        for (int nf = 0; nf < 16; nf++) {
            int c = nf * 8 + 2 * qk;
            float2 b2 = *(const float2*)&br2s[c];
            float2 be = *(const float2*)&be2s[c];
            if (e0 < E) {
                float2 o;
                o.x = silu_f(C2[nf][0] + b2.x) + silu_f(CE[nf][0] + be.x);
                o.y = silu_f(C2[nf][1] + b2.y) + silu_f(CE[nf][1] + be.y);
                *(float2*)&p0[c] = o;
            }
            if (e1_ < E) {
                float2 o;
                o.x = silu_f(C2[nf][2] + b2.x) + silu_f(CE[nf][2] + be.x);
                o.y = silu_f(C2[nf][3] + b2.y) + silu_f(CE[nf][3] + be.y);
                *(float2*)&p1[c] = o;
            }
        }
    }
}

// ---------------------------------------------------------------------------
// Node kernel (unchanged, ~134us)
// ---------------------------------------------------------------------------
__global__ __launch_bounds__(264, 2)
void node_kernel(const float* __restrict__ inv_f, const float* __restrict__ ev_f,
                 const float* __restrict__ w_int, const float* __restrict__ b_int,
                 float* __restrict__ out_inv, float* __restrict__ out_ev, int N)
{
    extern __shared__ float sm[];
    float* Wsh = sm;
    float* bsh = Wsh + 17424;
    float* xs  = bsh + 132;
    float* aev = xs + 4224;

    const int tx  = threadIdx.x;
    const int ty  = threadIdx.y;
    const int tid = tx + 33 * ty;
    const int NT  = 264;

    for (int i = tid; i < 17424; i += NT) Wsh[i] = w_int[i];
    if (tid < 132) bsh[tid] = b_int[tid];
    __syncthreads();

    const int nTiles = (N + 31) / 32;
    for (int tile = blockIdx.x; tile < nTiles; tile += gridDim.x) {
        const int base = tile * 32;

        for (int i = tid; i < 32 * 132; i += NT) {
            int l = i / 132, c = i % 132;
            int n = base + l;
            float v = 0.0f;
            if (n < N) {
                if (c < 128) {
                    v = 2.0f * inv_f[(size_t)n * 128 + c];
                } else {
                    const int st[5] = {0, 1, 4, 9, 16};
                    int s = c - 128;
                    float acc = 0.0f;
                    for (int k = st[s]; k < st[s + 1]; k++) {
                        float a = 2.0f * ev_f[(size_t)n * 16 + k];
                        acc = fmaf(a, a, acc);
                    }
                    v = acc;
                }
            }
            xs[l * 132 + c] = v;
        }
        for (int i = tid; i < 512; i += NT) {
            int l = i / 16, k = i % 16;
            int n = base + l;
            aev[i] = (n < N) ? 2.0f * ev_f[(size_t)n * 16 + k] : 0.0f;
        }
        __syncthreads();

        const int c0 = tx * 4;
        float acc[4][4];
        #pragma unroll
        for (int i = 0; i < 4; i++)
            #pragma unroll
            for (int k = 0; k < 4; k++) acc[i][k] = 0.0f;

        #pragma unroll 4
        for (int j = 0; j < 132; j++) {
            float4 w4 = *(const float4*)&Wsh[j * 132 + c0];
            #pragma unroll
            for (int i = 0; i < 4; i++) {
                float xv = xs[(ty * 4 + i) * 132 + j];
                acc[i][0] = fmaf(xv, w4.x, acc[i][0]);
                acc[i][1] = fmaf(xv, w4.y, acc[i][1]);
                acc[i][2] = fmaf(xv, w4.z, acc[i][2]);
                acc[i][3] = fmaf(xv, w4.w, acc[i][3]);
            }
        }

        const float4 bv = *(const float4*)&bsh[c0];
        #pragma unroll
        for (int i = 0; i < 4; i++) {
            int n = base + ty * 4 + i;
            if (n >= N) continue;
            float t0 = acc[i][0] + bv.x;
            float t1 = acc[i][1] + bv.y;
            float t2 = acc[i][2] + bv.z;
            float t3 = acc[i][3] + bv.w;
            if (tx < 32) {
                float4 o;
                o.x = xs[(ty * 4 + i) * 132 + c0 + 0] + t0;
                o.y = xs[(ty * 4 + i) * 132 + c0 + 1] + t1;
                o.z = xs[(ty * 4 + i) * 132 + c0 + 2] + t2;
                o.w = xs[(ty * 4 + i) * 132 + c0 + 3] + t3;
                *(float4*)&out_inv[(size_t)n * 128 + c0] = o;
            } else {
                float tb[4] = {t0, t1, t2, t3};
                const int SEG[16] = {0,1,1,1,2,2,2,2,2,3,3,3,3,3,3,3};
                #pragma unroll
                for (int k = 0; k < 16; k++) {
                    out_ev[(size_t)n * 16 + k] =
                        aev[(ty * 4 + i) * 16 + k] * (1.0f + tb[SEG[k]]);
                }
            }
        }
        __syncthreads();
    }
}

static const int NODE_SMEM = 22292 * 4;

extern "C" void kernel_launch(void* const* d_in, const int* in_sizes, int n_in,
                              void* d_out, int out_size)
{
    const float* inv_f     = (const float*)d_in[0];
    const float* ev_f      = (const float*)d_in[1];
    const int*   senders   = (const int*)  d_in[2];
    const int*   receivers = (const int*)  d_in[3];
    const float* lengths   = (const float*)d_in[5];

    const float* fi_rbf_w1 = (const float*)d_in[7];
    const float* fi_rbf_b1 = (const float*)d_in[8];
    const float* fi_rbf_w2 = (const float*)d_in[9];
    const float* fi_rbf_b2 = (const float*)d_in[10];
    const float* fi_ev_w1  = (const float*)d_in[11];
    const float* fi_ev_b1  = (const float*)d_in[12];
    const float* fi_ev_w2  = (const float*)d_in[13];
    const float* fi_ev_b2  = (const float*)d_in[14];
    const float* fe_rbf_w1 = (const float*)d_in[15];
    const float* fe_rbf_b1 = (const float*)d_in[16];
    const float* fe_rbf_w2 = (const float*)d_in[17];
    const float* fe_rbf_b2 = (const float*)d_in[18];
    const float* fe_ev_w1  = (const float*)d_in[19];
    const float* fe_ev_b1  = (const float*)d_in[20];
    const float* fe_ev_w2  = (const float*)d_in[21];
    const float* fe_ev_b2  = (const float*)d_in[22];
    const float* w_int     = (const float*)d_in[23];
    const float* b_int     = (const float*)d_in[24];

    const int N = in_sizes[0] / 128;
    const int E = in_sizes[2];

    float* out     = (float*)d_out;
    float* out_inv = out;
    float* out_ev  = out + (size_t)N * 128;
    float* fw_inv  = out + (size_t)N * 144;
    float* fw_ev   = fw_inv + (size_t)E * 128;

    cudaFuncSetAttribute(node_kernel,
                         cudaFuncAttributeMaxDynamicSharedMemorySize, NODE_SMEM);
    cudaFuncSetAttribute(edge_filter_mma,
                         cudaFuncAttributeMaxDynamicSharedMemorySize, EDGE_SMEM);

    edge_filter_mma<<<148, 384, EDGE_SMEM>>>(
        ev_f, senders, receivers, lengths,
        fi_rbf_w1, fi_rbf_b1, fi_rbf_w2, fi_rbf_b2,
        fi_ev_w1,  fi_ev_b1,  fi_ev_w2,  fi_ev_b2,
        fw_inv, E);

    edge_filter_mma<<<148, 384, EDGE_SMEM>>>(
        ev_f, senders, receivers, lengths,
        fe_rbf_w1, fe_rbf_b1, fe_rbf_w2, fe_rbf_b2,
        fe_ev_w1,  fe_ev_b1,  fe_ev_w2,  fe_ev_b2,
        fw_ev, E);

    node_kernel<<<304, dim3(33, 8), NODE_SMEM>>>(
        inv_f, ev_f, w_int, b_int, out_inv, out_ev, N);
}